// round 1
// baseline (speedup 1.0000x reference)
#include <cuda_runtime.h>
#include <math.h>

// Problem constants
#define TSTEPS 512
#define B_ 256
#define H_ 1024
#define K_ 1024

// Ping-pong hidden-state buffer (device global; allocation-free rule)
__device__ float g_h[2][B_ * H_];

// ---------------------------------------------------------------------------
// Zero the initial hidden state (must run every call: graph replays reuse
// g_h, and determinism requires h0 = 0 each time).
// ---------------------------------------------------------------------------
__global__ void zero_h0_kernel() {
    int i = blockIdx.x * blockDim.x + threadIdx.x;
    g_h[0][i] = 0.0f;
}

// ---------------------------------------------------------------------------
// Phase 1: xp[m, n] = sum_k x[m, k] * Wx[n, k] + bx[n]
//   A = x   : [M = T*B, K] row-major
//   W = Wx  : [H, K]       row-major (nn.Linear layout, so C = A @ W^T)
//   C = xp  : [M, H]       row-major  (written into the h_all region of d_out)
// Tiling: 128x128 block tile, BK=8, 256 threads, 8x8 per thread.
// ---------------------------------------------------------------------------
__global__ void __launch_bounds__(256, 2) gemm_xp_kernel(
    const float* __restrict__ A, const float* __restrict__ W,
    const float* __restrict__ bias, float* __restrict__ C)
{
    constexpr int BM = 128, BN = 128, BK = 8, TM = 8, TN = 8;
    __shared__ float As[BK][BM];
    __shared__ float Bs[BK][BN];

    const int tid  = threadIdx.x;
    const int row0 = blockIdx.y * BM;   // M offset
    const int col0 = blockIdx.x * BN;   // N (hidden) offset

    // Load indices: 128 rows x 8 cols tile of A (1024 floats = 256 * float4)
    const int aRow = tid / 2;            // 0..127
    const int aCol = (tid % 2) * 4;      // 0 or 4
    const int bRow = tid / 2;            // 0..127 (n index)
    const int bCol = (tid % 2) * 4;      // 0 or 4 (k index)

    // Compute mapping: 16 x 16 thread grid, 8x8 micro tile
    const int tr = (tid / 16) * TM;
    const int tc = (tid % 16) * TN;

    float acc[TM][TN] = {};

    for (int k0 = 0; k0 < K_; k0 += BK) {
        float4 av = *reinterpret_cast<const float4*>(
            &A[(size_t)(row0 + aRow) * K_ + k0 + aCol]);
        As[aCol + 0][aRow] = av.x;
        As[aCol + 1][aRow] = av.y;
        As[aCol + 2][aRow] = av.z;
        As[aCol + 3][aRow] = av.w;

        float4 wv = *reinterpret_cast<const float4*>(
            &W[(size_t)(col0 + bRow) * K_ + k0 + bCol]);
        Bs[bCol + 0][bRow] = wv.x;
        Bs[bCol + 1][bRow] = wv.y;
        Bs[bCol + 2][bRow] = wv.z;
        Bs[bCol + 3][bRow] = wv.w;

        __syncthreads();

        #pragma unroll
        for (int k = 0; k < BK; k++) {
            float ra[TM], rb[TN];
            #pragma unroll
            for (int i = 0; i < TM; i++) ra[i] = As[k][tr + i];
            #pragma unroll
            for (int j = 0; j < TN; j++) rb[j] = Bs[k][tc + j];
            #pragma unroll
            for (int i = 0; i < TM; i++)
                #pragma unroll
                for (int j = 0; j < TN; j++)
                    acc[i][j] += ra[i] * rb[j];
        }
        __syncthreads();
    }

    #pragma unroll
    for (int i = 0; i < TM; i++) {
        #pragma unroll
        for (int j = 0; j < TN; j += 4) {
            float4 v;
            v.x = acc[i][j + 0] + bias[col0 + tc + j + 0];
            v.y = acc[i][j + 1] + bias[col0 + tc + j + 1];
            v.z = acc[i][j + 2] + bias[col0 + tc + j + 2];
            v.w = acc[i][j + 3] + bias[col0 + tc + j + 3];
            *reinterpret_cast<float4*>(
                &C[(size_t)(row0 + tr + i) * H_ + col0 + tc + j]) = v;
        }
    }
}

// ---------------------------------------------------------------------------
// Phase 2: one recurrence step.
//   h_new[b, n] = tanh( xp[t, b, n] + sum_k h_prev[b, k] * Wh[n, k] + bh[n] )
// Reads xp row t from the h_all region and overwrites it in place with h_t.
// Tiling: BM=64 (batch) x BN=32 (hidden), BK=16, 128 threads, 4x4 per thread
//   -> grid = (1024/32) x (256/64) = 32 x 4 = 128 blocks (~1 wave on 148 SMs).
// ---------------------------------------------------------------------------
__global__ void __launch_bounds__(128) rnn_step_kernel(
    const float* __restrict__ Wh, const float* __restrict__ bh,
    float* __restrict__ hall, float* __restrict__ hfinal, int t)
{
    constexpr int BM = 64, BN = 32, BK = 16, TM = 4, TN = 4;
    __shared__ float As[BK][BM];
    __shared__ float Bs[BK][BN];

    const float* __restrict__ Hprev = g_h[t & 1];
    float* __restrict__ Hnew        = g_h[(t + 1) & 1];
    float* __restrict__ xp          = hall + (size_t)t * B_ * H_;

    const int tid  = threadIdx.x;
    const int row0 = blockIdx.y * BM;   // batch offset
    const int col0 = blockIdx.x * BN;   // hidden offset

    // A tile: 64 rows (batch) x 16 cols (k) = 1024 floats = 128 thr * 2 * float4
    const int aRow = tid / 4;            // 0..31 (+32 on second pass)
    const int aCol = (tid % 4) * 4;      // 0,4,8,12
    // B tile: 32 rows (n) x 16 cols (k) = 512 floats = 128 thr * float4
    const int bRow = tid / 4;            // 0..31
    const int bCol = (tid % 4) * 4;

    const int tr = (tid / 8) * TM;       // 0..60
    const int tc = (tid % 8) * TN;       // 0..28

    float acc[TM][TN] = {};

    for (int k0 = 0; k0 < H_; k0 += BK) {
        #pragma unroll
        for (int r = 0; r < 2; r++) {
            float4 av = *reinterpret_cast<const float4*>(
                &Hprev[(size_t)(row0 + aRow + 32 * r) * H_ + k0 + aCol]);
            As[aCol + 0][aRow + 32 * r] = av.x;
            As[aCol + 1][aRow + 32 * r] = av.y;
            As[aCol + 2][aRow + 32 * r] = av.z;
            As[aCol + 3][aRow + 32 * r] = av.w;
        }
        float4 wv = *reinterpret_cast<const float4*>(
            &Wh[(size_t)(col0 + bRow) * H_ + k0 + bCol]);
        Bs[bCol + 0][bRow] = wv.x;
        Bs[bCol + 1][bRow] = wv.y;
        Bs[bCol + 2][bRow] = wv.z;
        Bs[bCol + 3][bRow] = wv.w;

        __syncthreads();

        #pragma unroll
        for (int k = 0; k < BK; k++) {
            float ra[TM], rb[TN];
            #pragma unroll
            for (int i = 0; i < TM; i++) ra[i] = As[k][tr + i];
            #pragma unroll
            for (int j = 0; j < TN; j++) rb[j] = Bs[k][tc + j];
            #pragma unroll
            for (int i = 0; i < TM; i++)
                #pragma unroll
                for (int j = 0; j < TN; j++)
                    acc[i][j] += ra[i] * rb[j];
        }
        __syncthreads();
    }

    #pragma unroll
    for (int i = 0; i < TM; i++) {
        const size_t rowIdx = (size_t)(row0 + tr + i) * H_;
        #pragma unroll
        for (int j = 0; j < TN; j++) {
            const int col = col0 + tc + j;
            float v = tanhf(acc[i][j] + xp[rowIdx + col] + bh[col]);
            Hnew[rowIdx + col] = v;
            xp[rowIdx + col]   = v;           // h_all[t] overwrites xp[t] in place
            if (hfinal) hfinal[rowIdx + col] = v;
        }
    }
}

// ---------------------------------------------------------------------------
// Launch: zero h0, one big GEMM for xp (into the h_all slab), then 512
// sequential step kernels. All graph-capturable; no allocs, no syncs.
// Inputs (metadata order): x, Wx, bx, Wh, bh. Output: [h_final | h_all].
// ---------------------------------------------------------------------------
extern "C" void kernel_launch(void* const* d_in, const int* in_sizes, int n_in,
                              void* d_out, int out_size)
{
    const float* x  = (const float*)d_in[0];
    const float* Wx = (const float*)d_in[1];
    const float* bx = (const float*)d_in[2];
    const float* Wh = (const float*)d_in[3];
    const float* bh = (const float*)d_in[4];

    float* out    = (float*)d_out;
    float* hfinal = out;                 // [B_ * H_]
    float* hall   = out + B_ * H_;       // [TSTEPS * B_ * H_]

    // h0 = 0 (every call — graph replays must be deterministic)
    zero_h0_kernel<<<(B_ * H_) / 256, 256>>>();

    // Phase 1: xp for all timesteps in one GEMM, written into h_all slab
    dim3 g1(H_ / 128, (TSTEPS * B_) / 128);
    gemm_xp_kernel<<<g1, 256>>>(x, Wx, bx, hall);

    // Phase 2: sequential scan
    dim3 g2(H_ / 32, B_ / 64);
    for (int t = 0; t < TSTEPS; t++) {
        rnn_step_kernel<<<g2, 128>>>(Wh, bh, hall,
                                     (t == TSTEPS - 1) ? hfinal : nullptr, t);
    }
}

// round 3
// speedup vs baseline: 2.1918x; 2.1918x over previous
#include <cuda_runtime.h>
#include <cuda_bf16.h>
#include <stdint.h>
#include <math.h>

// Problem constants
#define TSTEPS 512
#define B_ 256
#define H_ 1024
#define K_ 1024
#define BH_ (B_ * H_)

// ---------------------------------------------------------------------------
// Helpers
// ---------------------------------------------------------------------------
__device__ __forceinline__ uint32_t smem_u32(const void* p) {
    uint32_t a;
    asm("{ .reg .u64 t; cvta.to.shared.u64 t, %1; cvt.u32.u64 %0, t; }"
        : "=r"(a) : "l"(p));
    return a;
}
__device__ __forceinline__ uint32_t sw128(uint32_t off) {
    return off ^ ((off >> 3) & 0x70);
}
__device__ __forceinline__ void ldsm4(uint32_t r[4], uint32_t addr) {
    asm volatile("ldmatrix.sync.aligned.m8n8.x4.shared.b16 {%0,%1,%2,%3}, [%4];"
                 : "=r"(r[0]), "=r"(r[1]), "=r"(r[2]), "=r"(r[3]) : "r"(addr));
}
__device__ __forceinline__ void mma_bf16(float c[4], const uint32_t a[4],
                                         uint32_t b0, uint32_t b1) {
    asm volatile(
        "mma.sync.aligned.m16n8k16.row.col.f32.bf16.bf16.f32 "
        "{%0,%1,%2,%3}, {%4,%5,%6,%7}, {%8,%9}, {%0,%1,%2,%3};"
        : "+f"(c[0]), "+f"(c[1]), "+f"(c[2]), "+f"(c[3])
        : "r"(a[0]), "r"(a[1]), "r"(a[2]), "r"(a[3]), "r"(b0), "r"(b1));
}
__device__ __forceinline__ uint32_t pack2(__nv_bfloat16 a, __nv_bfloat16 b) {
    return ((uint32_t)__bfloat16_as_ushort(b) << 16) | __bfloat16_as_ushort(a);
}
// Split float4 -> (hi bf16x2 pair, lo bf16x2 pair) : two 8B stores
__device__ __forceinline__ void split_store(float4 v, char* hiBase, char* loBase,
                                            uint32_t off) {
    __nv_bfloat16 h0 = __float2bfloat16(v.x);
    __nv_bfloat16 h1 = __float2bfloat16(v.y);
    __nv_bfloat16 h2 = __float2bfloat16(v.z);
    __nv_bfloat16 h3 = __float2bfloat16(v.w);
    float l0 = v.x - __bfloat162float(h0);
    float l1 = v.y - __bfloat162float(h1);
    float l2 = v.z - __bfloat162float(h2);
    float l3 = v.w - __bfloat162float(h3);
    uint32_t s = sw128(off);
    *(uint2*)(hiBase + s) = make_uint2(pack2(h0, h1), pack2(h2, h3));
    *(uint2*)(loBase + s) = make_uint2(pack2(__float2bfloat16(l0), __float2bfloat16(l1)),
                                       pack2(__float2bfloat16(l2), __float2bfloat16(l3)));
}

// ---------------------------------------------------------------------------
// Phase 1: xp[m,n] = x[m,:] . Wx[n,:] + bx[n]   (3-term bf16 HMMA)
// BM=128, BN=64, CK=64, 256 threads (8 warps, 4m x 2n, warp tile 32x32)
// grid = (16 n-tiles, 1024 m-tiles); n-tiles on consecutive bids for L2 reuse.
// ---------------------------------------------------------------------------
__global__ void __launch_bounds__(256, 1) gemm_xp_kernel(
    const float* __restrict__ A, const float* __restrict__ W,
    const float* __restrict__ bias, float* __restrict__ C)
{
    __shared__ __align__(1024) char sAh[128 * 128];   // 16KB
    __shared__ __align__(1024) char sAl[128 * 128];
    __shared__ __align__(1024) char sBh[64 * 128];    // 8KB
    __shared__ __align__(1024) char sBl[64 * 128];

    const int tid = threadIdx.x;
    const int wid = tid >> 5, lane = tid & 31;
    const int m0 = blockIdx.y * 128;
    const int n0 = blockIdx.x * 64;
    const int wm = (wid >> 1) * 32;      // 0,32,64,96
    const int wn = (wid & 1) * 32;       // 0,32

    const uint32_t uAh = smem_u32(sAh), uAl = smem_u32(sAl);
    const uint32_t uBh = smem_u32(sBh), uBl = smem_u32(sBl);

    const int ar = tid >> 4;             // 0..15
    const int ac = tid & 15;             // 0..15 (float4 col)
    const float4* __restrict__ A4 = (const float4*)A;
    const float4* __restrict__ W4 = (const float4*)W;

    float c[2][4][4] = {};               // [mi][ni][reg]
    float4 pa[8], pb[4];

    // prefetch chunk 0
    #pragma unroll
    for (int p = 0; p < 8; p++)
        pa[p] = A4[(size_t)(m0 + ar + p * 16) * 256 + ac];
    #pragma unroll
    for (int p = 0; p < 4; p++)
        pb[p] = W4[(size_t)(n0 + ar + p * 16) * 256 + ac];

    for (int ch = 0; ch < 16; ch++) {
        if (ch > 0) __syncthreads();
        // stage (convert + swizzled store)
        #pragma unroll
        for (int p = 0; p < 8; p++)
            split_store(pa[p], sAh, sAl, (uint32_t)((ar + p * 16) * 128 + ac * 8));
        #pragma unroll
        for (int p = 0; p < 4; p++)
            split_store(pb[p], sBh, sBl, (uint32_t)((ar + p * 16) * 128 + ac * 8));
        __syncthreads();

        // prefetch next chunk (overlaps MMA below)
        if (ch < 15) {
            const int kc = (ch + 1) * 16;
            #pragma unroll
            for (int p = 0; p < 8; p++)
                pa[p] = A4[(size_t)(m0 + ar + p * 16) * 256 + kc + ac];
            #pragma unroll
            for (int p = 0; p < 4; p++)
                pb[p] = W4[(size_t)(n0 + ar + p * 16) * 256 + kc + ac];
        }

        #pragma unroll
        for (int ks = 0; ks < 4; ks++) {
            const int q = lane >> 3;
            uint32_t ah[2][4], al[2][4];
            #pragma unroll
            for (int mi = 0; mi < 2; mi++) {
                uint32_t r = (uint32_t)(wm + mi * 16 + (lane & 7) + (q & 1) * 8);
                uint32_t kb = (uint32_t)(ks * 32 + (q >> 1) * 16);
                uint32_t so = sw128(r * 128 + kb);
                ldsm4(ah[mi], uAh + so);
                ldsm4(al[mi], uAl + so);
            }
            uint32_t bhf[2][4], blf[2][4];
            #pragma unroll
            for (int g = 0; g < 2; g++) {
                uint32_t rn = (uint32_t)(wn + g * 16 + (lane & 7) + (q >> 1) * 8);
                uint32_t kb = (uint32_t)(ks * 32 + (q & 1) * 16);
                uint32_t so = sw128(rn * 128 + kb);
                ldsm4(bhf[g], uBh + so);
                ldsm4(blf[g], uBl + so);
            }
            #pragma unroll
            for (int mi = 0; mi < 2; mi++)
                #pragma unroll
                for (int ni = 0; ni < 4; ni++) {
                    uint32_t b0h = bhf[ni >> 1][(ni & 1) * 2];
                    uint32_t b1h = bhf[ni >> 1][(ni & 1) * 2 + 1];
                    uint32_t b0l = blf[ni >> 1][(ni & 1) * 2];
                    uint32_t b1l = blf[ni >> 1][(ni & 1) * 2 + 1];
                    mma_bf16(c[mi][ni], ah[mi], b0h, b1h);
                    mma_bf16(c[mi][ni], ah[mi], b0l, b1l);
                    mma_bf16(c[mi][ni], al[mi], b0h, b1h);
                }
        }
    }

    // epilogue: + bias, store fp32
    const int t4 = lane >> 2, cp = (lane & 3) * 2;
    #pragma unroll
    for (int mi = 0; mi < 2; mi++) {
        #pragma unroll
        for (int ni = 0; ni < 4; ni++) {
            const int col = n0 + wn + ni * 8 + cp;
            float2 bv = *(const float2*)&bias[col];
            const int r0 = m0 + wm + mi * 16 + t4;
            float2 v0 = make_float2(c[mi][ni][0] + bv.x, c[mi][ni][1] + bv.y);
            float2 v1 = make_float2(c[mi][ni][2] + bv.x, c[mi][ni][3] + bv.y);
            *(float2*)&C[(size_t)r0 * H_ + col] = v0;
            *(float2*)&C[(size_t)(r0 + 8) * H_ + col] = v1;
        }
    }
}

// ---------------------------------------------------------------------------
// Phase 2 step: h_t = tanh(h_{t-1} @ Wh^T + xp_t + bh)   (3-term bf16 HMMA)
// BM=64, BN=32, CK=64, 128 threads (4 warps, 2m x 2n, warp tile 32x16)
// grid = (32 n-tiles, 4 m-tiles) = 128 CTAs.
// A = hall[t-1] fp32 (skipped at t=0), output overwrites hall[t] (= xp row t).
// ---------------------------------------------------------------------------
__global__ void __launch_bounds__(128, 1) rnn_step_kernel(
    const float* __restrict__ Wh, const float* __restrict__ bh,
    float* __restrict__ hall, float* __restrict__ hfinal, int t)
{
    __shared__ __align__(1024) char sAh[64 * 128];   // 8KB
    __shared__ __align__(1024) char sAl[64 * 128];
    __shared__ __align__(1024) char sBh[32 * 128];   // 4KB
    __shared__ __align__(1024) char sBl[32 * 128];

    const int tid = threadIdx.x;
    const int wid = tid >> 5, lane = tid & 31;
    const int m0 = blockIdx.y * 64;
    const int n0 = blockIdx.x * 32;
    const int wm = (wid >> 1) * 32;      // 0,32
    const int wn = (wid & 1) * 16;       // 0,16

    const uint32_t uAh = smem_u32(sAh), uAl = smem_u32(sAl);
    const uint32_t uBh = smem_u32(sBh), uBl = smem_u32(sBl);

    const int ar = tid >> 4;             // 0..7
    const int ac = tid & 15;             // float4 col 0..15

    float c[2][2][4] = {};               // [mi][ni][reg]

    if (t > 0) {
        const float4* __restrict__ A4 = (const float4*)(hall + (size_t)(t - 1) * BH_);
        const float4* __restrict__ W4 = (const float4*)Wh;
        float4 pa[8], pb[4];

        #pragma unroll
        for (int p = 0; p < 8; p++)
            pa[p] = A4[(size_t)(m0 + ar + p * 8) * 256 + ac];
        #pragma unroll
        for (int p = 0; p < 4; p++)
            pb[p] = W4[(size_t)(n0 + ar + p * 8) * 256 + ac];

        for (int ch = 0; ch < 16; ch++) {
            if (ch > 0) __syncthreads();
            #pragma unroll
            for (int p = 0; p < 8; p++)
                split_store(pa[p], sAh, sAl, (uint32_t)((ar + p * 8) * 128 + ac * 8));
            #pragma unroll
            for (int p = 0; p < 4; p++)
                split_store(pb[p], sBh, sBl, (uint32_t)((ar + p * 8) * 128 + ac * 8));
            __syncthreads();

            if (ch < 15) {
                const int kc = (ch + 1) * 16;
                #pragma unroll
                for (int p = 0; p < 8; p++)
                    pa[p] = A4[(size_t)(m0 + ar + p * 8) * 256 + kc + ac];
                #pragma unroll
                for (int p = 0; p < 4; p++)
                    pb[p] = W4[(size_t)(n0 + ar + p * 8) * 256 + kc + ac];
            }

            #pragma unroll
            for (int ks = 0; ks < 4; ks++) {
                const int q = lane >> 3;
                uint32_t ah[2][4], al[2][4];
                #pragma unroll
                for (int mi = 0; mi < 2; mi++) {
                    uint32_t r = (uint32_t)(wm + mi * 16 + (lane & 7) + (q & 1) * 8);
                    uint32_t kb = (uint32_t)(ks * 32 + (q >> 1) * 16);
                    uint32_t so = sw128(r * 128 + kb);
                    ldsm4(ah[mi], uAh + so);
                    ldsm4(al[mi], uAl + so);
                }
                uint32_t bhf[4], blf[4];
                {
                    uint32_t rn = (uint32_t)(wn + (lane & 7) + (q >> 1) * 8);
                    uint32_t kb = (uint32_t)(ks * 32 + (q & 1) * 16);
                    uint32_t so = sw128(rn * 128 + kb);
                    ldsm4(bhf, uBh + so);
                    ldsm4(blf, uBl + so);
                }
                #pragma unroll
                for (int mi = 0; mi < 2; mi++)
                    #pragma unroll
                    for (int ni = 0; ni < 2; ni++) {
                        uint32_t b0h = bhf[ni * 2], b1h = bhf[ni * 2 + 1];
                        uint32_t b0l = blf[ni * 2], b1l = blf[ni * 2 + 1];
                        mma_bf16(c[mi][ni], ah[mi], b0h, b1h);
                        mma_bf16(c[mi][ni], ah[mi], b0l, b1l);
                        mma_bf16(c[mi][ni], al[mi], b0h, b1h);
                    }
            }
        }
    }

    // Epilogue: h = tanh(C + xp + bh); overwrite hall[t]; optional hfinal.
    float* __restrict__ xp = hall + (size_t)t * BH_;
    const int t4 = lane >> 2, cp = (lane & 3) * 2;
    #pragma unroll
    for (int mi = 0; mi < 2; mi++) {
        #pragma unroll
        for (int ni = 0; ni < 2; ni++) {
            const int col = n0 + wn + ni * 8 + cp;
            float2 bv = *(const float2*)&bh[col];
            #pragma unroll
            for (int h = 0; h < 2; h++) {
                const int r = m0 + wm + mi * 16 + t4 + h * 8;
                float2 xv = *(const float2*)&xp[(size_t)r * H_ + col];
                float v0 = tanhf(c[mi][ni][h * 2]     + xv.x + bv.x);
                float v1 = tanhf(c[mi][ni][h * 2 + 1] + xv.y + bv.y);
                *(float2*)&xp[(size_t)r * H_ + col] = make_float2(v0, v1);
                if (hfinal)
                    *(float2*)&hfinal[(size_t)r * H_ + col] = make_float2(v0, v1);
            }
        }
    }
}

// ---------------------------------------------------------------------------
// kernel_launch: phase-1 GEMM into h_all slab, then 512 sequential steps.
// Graph-capturable; no allocations, no syncs, no prep kernels.
// ---------------------------------------------------------------------------
extern "C" void kernel_launch(void* const* d_in, const int* in_sizes, int n_in,
                              void* d_out, int out_size)
{
    const float* x  = (const float*)d_in[0];
    const float* Wx = (const float*)d_in[1];
    const float* bx = (const float*)d_in[2];
    const float* Wh = (const float*)d_in[3];
    const float* bh = (const float*)d_in[4];

    float* out    = (float*)d_out;
    float* hfinal = out;                 // [B_ * H_]
    float* hall   = out + BH_;           // [TSTEPS * B_ * H_]

    // Phase 1: xp for all timesteps (n-tiles on blockIdx.x for L2 reuse of x)
    gemm_xp_kernel<<<dim3(16, 1024), 256>>>(x, Wx, bx, hall);

    // Phase 2: sequential scan
    for (int t = 0; t < TSTEPS; t++) {
        rnn_step_kernel<<<dim3(32, 4), 128>>>(
            Wh, bh, hall, (t == TSTEPS - 1) ? hfinal : (float*)0, t);
    }
}

// round 4
// speedup vs baseline: 2.7695x; 1.2636x over previous
#include <cuda_runtime.h>
#include <cuda_bf16.h>
#include <stdint.h>
#include <math.h>

// Problem constants
#define TSTEPS 512
#define B_ 256
#define H_ 1024
#define K_ 1024
#define BH_ (B_ * H_)

#define NBLOCKS 128          // persistent scan grid (32 n-tiles x 4 m-tiles)

// Persistent-kernel SMEM map (dynamic)
#define OFF_WHH  0            // 16 chunks x 4KB (32n x 64k bf16 hi)
#define OFF_WHL  65536        // lo
#define OFF_ABUF 131072       // 2 bufs x (8KB hi + 8KB lo)
#define ABUF_STRIDE 16384
#define SMEM_TOTAL 163840     // 160 KB -> 1 CTA/SM

// ---------------------------------------------------------------------------
// Helpers
// ---------------------------------------------------------------------------
__device__ __forceinline__ uint32_t smem_u32(const void* p) {
    uint32_t a;
    asm("{ .reg .u64 t; cvta.to.shared.u64 t, %1; cvt.u32.u64 %0, t; }"
        : "=r"(a) : "l"(p));
    return a;
}
__device__ __forceinline__ uint32_t sw128(uint32_t off) {
    return off ^ ((off >> 3) & 0x70);
}
__device__ __forceinline__ void ldsm4(uint32_t r[4], uint32_t addr) {
    asm volatile("ldmatrix.sync.aligned.m8n8.x4.shared.b16 {%0,%1,%2,%3}, [%4];"
                 : "=r"(r[0]), "=r"(r[1]), "=r"(r[2]), "=r"(r[3]) : "r"(addr));
}
__device__ __forceinline__ void mma_bf16(float c[4], const uint32_t a[4],
                                         uint32_t b0, uint32_t b1) {
    asm volatile(
        "mma.sync.aligned.m16n8k16.row.col.f32.bf16.bf16.f32 "
        "{%0,%1,%2,%3}, {%4,%5,%6,%7}, {%8,%9}, {%0,%1,%2,%3};"
        : "+f"(c[0]), "+f"(c[1]), "+f"(c[2]), "+f"(c[3])
        : "r"(a[0]), "r"(a[1]), "r"(a[2]), "r"(a[3]), "r"(b0), "r"(b1));
}
__device__ __forceinline__ uint32_t pack2(__nv_bfloat16 a, __nv_bfloat16 b) {
    return ((uint32_t)__bfloat16_as_ushort(b) << 16) | __bfloat16_as_ushort(a);
}
__device__ __forceinline__ void split_store(float4 v, char* hiBase, char* loBase,
                                            uint32_t off) {
    __nv_bfloat16 h0 = __float2bfloat16(v.x);
    __nv_bfloat16 h1 = __float2bfloat16(v.y);
    __nv_bfloat16 h2 = __float2bfloat16(v.z);
    __nv_bfloat16 h3 = __float2bfloat16(v.w);
    float l0 = v.x - __bfloat162float(h0);
    float l1 = v.y - __bfloat162float(h1);
    float l2 = v.z - __bfloat162float(h2);
    float l3 = v.w - __bfloat162float(h3);
    uint32_t s = sw128(off);
    *(uint2*)(hiBase + s) = make_uint2(pack2(h0, h1), pack2(h2, h3));
    *(uint2*)(loBase + s) = make_uint2(pack2(__float2bfloat16(l0), __float2bfloat16(l1)),
                                       pack2(__float2bfloat16(l2), __float2bfloat16(l3)));
}

// ---------------------------------------------------------------------------
// Device-wide epoch barrier (graph-replay safe: epoch is monotonic, count
// resets to 0 every barrier). All 128 CTAs are resident (1/SM by SMEM).
// ---------------------------------------------------------------------------
__device__ unsigned g_count;
__device__ unsigned g_epoch;

__device__ __forceinline__ void grid_bar() {
    __threadfence();
    __syncthreads();
    if (threadIdx.x == 0) {
        unsigned e;
        asm volatile("ld.acquire.gpu.u32 %0, [%1];" : "=r"(e) : "l"(&g_epoch));
        unsigned prev;
        asm volatile("atom.add.release.gpu.u32 %0, [%1], 1;"
                     : "=r"(prev) : "l"(&g_count));
        if (prev == NBLOCKS - 1) {
            asm volatile("st.relaxed.gpu.u32 [%0], %1;" :: "l"(&g_count), "r"(0u));
            asm volatile("st.release.gpu.u32 [%0], %1;" :: "l"(&g_epoch), "r"(e + 1));
        } else {
            unsigned cur;
            do {
                __nanosleep(32);
                asm volatile("ld.acquire.gpu.u32 %0, [%1];" : "=r"(cur) : "l"(&g_epoch));
            } while (cur == e);
        }
    }
    __syncthreads();
}

// ---------------------------------------------------------------------------
// Phase 1: xp[m,n] = x[m,:] . Wx[n,:] + bx[n]   (3-term bf16 HMMA; unchanged)
// ---------------------------------------------------------------------------
__global__ void __launch_bounds__(256, 1) gemm_xp_kernel(
    const float* __restrict__ A, const float* __restrict__ W,
    const float* __restrict__ bias, float* __restrict__ C)
{
    __shared__ __align__(1024) char sAh[128 * 128];
    __shared__ __align__(1024) char sAl[128 * 128];
    __shared__ __align__(1024) char sBh[64 * 128];
    __shared__ __align__(1024) char sBl[64 * 128];

    const int tid = threadIdx.x;
    const int wid = tid >> 5, lane = tid & 31;
    const int m0 = blockIdx.y * 128;
    const int n0 = blockIdx.x * 64;
    const int wm = (wid >> 1) * 32;
    const int wn = (wid & 1) * 32;

    const uint32_t uAh = smem_u32(sAh), uAl = smem_u32(sAl);
    const uint32_t uBh = smem_u32(sBh), uBl = smem_u32(sBl);

    const int ar = tid >> 4;
    const int ac = tid & 15;
    const float4* __restrict__ A4 = (const float4*)A;
    const float4* __restrict__ W4 = (const float4*)W;

    float c[2][4][4] = {};
    float4 pa[8], pb[4];

    #pragma unroll
    for (int p = 0; p < 8; p++)
        pa[p] = A4[(size_t)(m0 + ar + p * 16) * 256 + ac];
    #pragma unroll
    for (int p = 0; p < 4; p++)
        pb[p] = W4[(size_t)(n0 + ar + p * 16) * 256 + ac];

    for (int ch = 0; ch < 16; ch++) {
        if (ch > 0) __syncthreads();
        #pragma unroll
        for (int p = 0; p < 8; p++)
            split_store(pa[p], sAh, sAl, (uint32_t)((ar + p * 16) * 128 + ac * 8));
        #pragma unroll
        for (int p = 0; p < 4; p++)
            split_store(pb[p], sBh, sBl, (uint32_t)((ar + p * 16) * 128 + ac * 8));
        __syncthreads();

        if (ch < 15) {
            const int kc = (ch + 1) * 16;
            #pragma unroll
            for (int p = 0; p < 8; p++)
                pa[p] = A4[(size_t)(m0 + ar + p * 16) * 256 + kc + ac];
            #pragma unroll
            for (int p = 0; p < 4; p++)
                pb[p] = W4[(size_t)(n0 + ar + p * 16) * 256 + kc + ac];
        }

        #pragma unroll
        for (int ks = 0; ks < 4; ks++) {
            const int q = lane >> 3;
            uint32_t ah[2][4], al[2][4];
            #pragma unroll
            for (int mi = 0; mi < 2; mi++) {
                uint32_t r = (uint32_t)(wm + mi * 16 + (lane & 7) + (q & 1) * 8);
                uint32_t kb = (uint32_t)(ks * 32 + (q >> 1) * 16);
                uint32_t so = sw128(r * 128 + kb);
                ldsm4(ah[mi], uAh + so);
                ldsm4(al[mi], uAl + so);
            }
            uint32_t bhf[2][4], blf[2][4];
            #pragma unroll
            for (int g = 0; g < 2; g++) {
                uint32_t rn = (uint32_t)(wn + g * 16 + (lane & 7) + (q >> 1) * 8);
                uint32_t kb = (uint32_t)(ks * 32 + (q & 1) * 16);
                uint32_t so = sw128(rn * 128 + kb);
                ldsm4(bhf[g], uBh + so);
                ldsm4(blf[g], uBl + so);
            }
            #pragma unroll
            for (int mi = 0; mi < 2; mi++)
                #pragma unroll
                for (int ni = 0; ni < 4; ni++) {
                    uint32_t b0h = bhf[ni >> 1][(ni & 1) * 2];
                    uint32_t b1h = bhf[ni >> 1][(ni & 1) * 2 + 1];
                    uint32_t b0l = blf[ni >> 1][(ni & 1) * 2];
                    uint32_t b1l = blf[ni >> 1][(ni & 1) * 2 + 1];
                    mma_bf16(c[mi][ni], ah[mi], b0h, b1h);
                    mma_bf16(c[mi][ni], ah[mi], b0l, b1l);
                    mma_bf16(c[mi][ni], al[mi], b0h, b1h);
                }
        }
    }

    const int t4 = lane >> 2, cp = (lane & 3) * 2;
    #pragma unroll
    for (int mi = 0; mi < 2; mi++) {
        #pragma unroll
        for (int ni = 0; ni < 4; ni++) {
            const int col = n0 + wn + ni * 8 + cp;
            float2 bv = *(const float2*)&bias[col];
            const int r0 = m0 + wm + mi * 16 + t4;
            float2 v0 = make_float2(c[mi][ni][0] + bv.x, c[mi][ni][1] + bv.y);
            float2 v1 = make_float2(c[mi][ni][2] + bv.x, c[mi][ni][3] + bv.y);
            *(float2*)&C[(size_t)r0 * H_ + col] = v0;
            *(float2*)&C[(size_t)(r0 + 8) * H_ + col] = v1;
        }
    }
}

// ---------------------------------------------------------------------------
// Phase 2: persistent scan kernel. Grid (32, 4) = 128 CTAs, 256 threads.
// Warps 0-3: MMA consumers (CTA tile M=64 x N=32, warp tile 32x16).
// Warps 4-7: producers (LDG h fp32 -> bf16 hi/lo split -> STS, double buffer).
// Wh tile (32n x 1024k) resident in SMEM as bf16 hi/lo, split once.
// Steps separated by device-wide barrier.
// ---------------------------------------------------------------------------
__global__ void __launch_bounds__(256, 1) rnn_scan_kernel(
    const float* __restrict__ Wh, const float* __restrict__ bh,
    float* __restrict__ hall, float* __restrict__ hfinal)
{
    extern __shared__ __align__(1024) char smem[];

    const int tid = threadIdx.x;
    const int wid = tid >> 5, lane = tid & 31;
    const int n0 = blockIdx.x * 32;      // hidden-tile base
    const int m0 = blockIdx.y * 64;      // batch-tile base

    const uint32_t uWhh = smem_u32(smem + OFF_WHH);
    const uint32_t uWhl = smem_u32(smem + OFF_WHL);
    const uint32_t uA   = smem_u32(smem + OFF_ABUF);

    // ---- one-time: split Wh tile into resident SMEM (16 chunks of 32x64) ----
    {
        const float4* __restrict__ W4 = (const float4*)Wh;
        for (int i = tid; i < 8192; i += 256) {
            int r  = i >> 8;          // 0..31 (n row)
            int f4 = i & 255;         // float4 col 0..255
            int c  = f4 >> 4;         // chunk
            int fc = f4 & 15;         // float4 within chunk
            float4 v = W4[(size_t)(n0 + r) * 256 + f4];
            split_store(v, smem + OFF_WHH + c * 4096, smem + OFF_WHL + c * 4096,
                        (uint32_t)(r * 128 + fc * 8));
        }
    }
    __syncthreads();

    // consumer-side constants
    const int t4 = lane >> 2, cp = (lane & 3) * 2;
    const int wm = (wid >> 1) * 32;      // consumer warp M offset (warps 0-3)
    const int wn = (wid & 1) * 16;       // consumer warp N offset
    float2 bv[2];                        // cached bias for this thread's cols
    if (wid < 4) {
        bv[0] = *(const float2*)&bh[n0 + wn + 0 + cp];
        bv[1] = *(const float2*)&bh[n0 + wn + 8 + cp];
    }

    // producer-side constants (warps 4-7)
    const int tid2 = tid & 127;
    const int ar = tid2 >> 4;            // 0..7
    const int ac = tid2 & 15;            // float4 col within chunk

    for (int t = 0; t < TSTEPS; t++) {
        float c[2][2][4] = {};

        if (t > 0) {
            const float4* __restrict__ A4 =
                (const float4*)(hall + (size_t)(t - 1) * BH_);
            float4 pa[8];
            if (wid >= 4) {
                #pragma unroll
                for (int p = 0; p < 8; p++)
                    pa[p] = A4[(size_t)(m0 + ar + p * 8) * 256 + ac];
            }
            for (int ch = 0; ch < 16; ch++) {
                if (wid >= 4) {
                    char* bufh = smem + OFF_ABUF + (ch & 1) * ABUF_STRIDE;
                    #pragma unroll
                    for (int p = 0; p < 8; p++)
                        split_store(pa[p], bufh, bufh + 8192,
                                    (uint32_t)((ar + p * 8) * 128 + ac * 8));
                    if (ch < 15) {
                        const int kc = (ch + 1) * 16;
                        #pragma unroll
                        for (int p = 0; p < 8; p++)
                            pa[p] = A4[(size_t)(m0 + ar + p * 8) * 256 + kc + ac];
                    }
                }
                __syncthreads();
                if (wid < 4) {
                    const uint32_t uAb = uA + (ch & 1) * ABUF_STRIDE;
                    #pragma unroll
                    for (int ks = 0; ks < 4; ks++) {
                        const int q = lane >> 3;
                        uint32_t ah[2][4], al[2][4];
                        #pragma unroll
                        for (int mi = 0; mi < 2; mi++) {
                            uint32_t r = (uint32_t)(wm + mi * 16 + (lane & 7) + (q & 1) * 8);
                            uint32_t kb = (uint32_t)(ks * 32 + (q >> 1) * 16);
                            uint32_t so = sw128(r * 128 + kb);
                            ldsm4(ah[mi], uAb + so);
                            ldsm4(al[mi], uAb + 8192 + so);
                        }
                        uint32_t bhf[4], blf[4];
                        {
                            uint32_t rn = (uint32_t)(wn + (lane & 7) + (q >> 1) * 8);
                            uint32_t kb = (uint32_t)(ks * 32 + (q & 1) * 16);
                            uint32_t so = sw128(rn * 128 + kb);
                            ldsm4(bhf, uWhh + ch * 4096 + so);
                            ldsm4(blf, uWhl + ch * 4096 + so);
                        }
                        #pragma unroll
                        for (int mi = 0; mi < 2; mi++)
                            #pragma unroll
                            for (int ni = 0; ni < 2; ni++) {
                                uint32_t b0h = bhf[ni * 2], b1h = bhf[ni * 2 + 1];
                                uint32_t b0l = blf[ni * 2], b1l = blf[ni * 2 + 1];
                                mma_bf16(c[mi][ni], ah[mi], b0h, b1h);
                                mma_bf16(c[mi][ni], ah[mi], b0l, b1l);
                                mma_bf16(c[mi][ni], al[mi], b0h, b1h);
                            }
                    }
                }
            }
        }

        // ---- epilogue (consumers): h = tanh(C + xp + bh) ----
        if (wid < 4) {
            float* __restrict__ xp = hall + (size_t)t * BH_;
            #pragma unroll
            for (int mi = 0; mi < 2; mi++) {
                #pragma unroll
                for (int ni = 0; ni < 2; ni++) {
                    const int col = n0 + wn + ni * 8 + cp;
                    #pragma unroll
                    for (int h = 0; h < 2; h++) {
                        const int r = m0 + wm + mi * 16 + t4 + h * 8;
                        float2 xv = *(const float2*)&xp[(size_t)r * H_ + col];
                        float v0 = tanhf(c[mi][ni][h * 2]     + xv.x + bv[ni].x);
                        float v1 = tanhf(c[mi][ni][h * 2 + 1] + xv.y + bv[ni].y);
                        *(float2*)&xp[(size_t)r * H_ + col] = make_float2(v0, v1);
                        if (t == TSTEPS - 1)
                            *(float2*)&hfinal[(size_t)r * H_ + col] =
                                make_float2(v0, v1);
                    }
                }
            }
        }

        if (t < TSTEPS - 1) grid_bar();
    }
}

// ---------------------------------------------------------------------------
// kernel_launch: phase-1 GEMM into h_all slab, then ONE persistent scan.
// Graph-capturable; no allocations, no syncs.
// ---------------------------------------------------------------------------
extern "C" void kernel_launch(void* const* d_in, const int* in_sizes, int n_in,
                              void* d_out, int out_size)
{
    const float* x  = (const float*)d_in[0];
    const float* Wx = (const float*)d_in[1];
    const float* bx = (const float*)d_in[2];
    const float* Wh = (const float*)d_in[3];
    const float* bh = (const float*)d_in[4];

    float* out    = (float*)d_out;
    float* hfinal = out;                 // [B_ * H_]
    float* hall   = out + BH_;           // [TSTEPS * B_ * H_]

    static int smem_set = 0;
    if (!smem_set) {
        cudaFuncSetAttribute(rnn_scan_kernel,
                             cudaFuncAttributeMaxDynamicSharedMemorySize,
                             SMEM_TOTAL);
        smem_set = 1;
    }

    // Phase 1: xp for all timesteps
    gemm_xp_kernel<<<dim3(16, 1024), 256>>>(x, Wx, bx, hall);

    // Phase 2: persistent tensor-core scan (128 CTAs, all resident)
    rnn_scan_kernel<<<dim3(32, 4), 256, SMEM_TOTAL>>>(Wh, bh, hall, hfinal);
}

// round 5
// speedup vs baseline: 3.4611x; 1.2497x over previous
#include <cuda_runtime.h>
#include <cuda_bf16.h>
#include <stdint.h>
#include <math.h>

// Problem constants
#define TSTEPS 512
#define B_ 256
#define H_ 1024
#define K_ 1024
#define BH_ (B_ * H_)

#define NBLOCKS 128          // persistent scan grid (32 n-tiles x 4 m-tiles)

// Persistent-kernel SMEM map (dynamic)
// Wh hi: 16 chunks x 4KB, Wh lo: same. A: 2 stages x 32KB
// (stage = 2 subchunks x {hi 8KB, lo 8KB})
#define OFF_WHH  0
#define OFF_WHL  65536
#define OFF_ABUF 131072
#define STAGE_STRIDE 32768
#define SMEM_TOTAL 196608     // 192 KB -> 1 CTA/SM

// h as pre-swizzled bf16 hi/lo blobs: [parity][mtile][subchunk][comp][64r x 64k]
__device__ __nv_bfloat16 g_hb[2][4][16][2][4096];

// ---------------------------------------------------------------------------
// Helpers
// ---------------------------------------------------------------------------
__device__ __forceinline__ uint32_t smem_u32(const void* p) {
    uint32_t a;
    asm("{ .reg .u64 t; cvta.to.shared.u64 t, %1; cvt.u32.u64 %0, t; }"
        : "=r"(a) : "l"(p));
    return a;
}
__device__ __forceinline__ uint32_t sw128(uint32_t off) {
    return off ^ ((off >> 3) & 0x70);
}
__device__ __forceinline__ void ldsm4(uint32_t r[4], uint32_t addr) {
    asm volatile("ldmatrix.sync.aligned.m8n8.x4.shared.b16 {%0,%1,%2,%3}, [%4];"
                 : "=r"(r[0]), "=r"(r[1]), "=r"(r[2]), "=r"(r[3]) : "r"(addr));
}
__device__ __forceinline__ void mma_bf16(float c[4], const uint32_t a[4],
                                         uint32_t b0, uint32_t b1) {
    asm volatile(
        "mma.sync.aligned.m16n8k16.row.col.f32.bf16.bf16.f32 "
        "{%0,%1,%2,%3}, {%4,%5,%6,%7}, {%8,%9}, {%0,%1,%2,%3};"
        : "+f"(c[0]), "+f"(c[1]), "+f"(c[2]), "+f"(c[3])
        : "r"(a[0]), "r"(a[1]), "r"(a[2]), "r"(a[3]), "r"(b0), "r"(b1));
}
__device__ __forceinline__ uint32_t pack2(__nv_bfloat16 a, __nv_bfloat16 b) {
    return ((uint32_t)__bfloat16_as_ushort(b) << 16) | __bfloat16_as_ushort(a);
}
__device__ __forceinline__ void split_store(float4 v, char* hiBase, char* loBase,
                                            uint32_t off) {
    __nv_bfloat16 h0 = __float2bfloat16(v.x);
    __nv_bfloat16 h1 = __float2bfloat16(v.y);
    __nv_bfloat16 h2 = __float2bfloat16(v.z);
    __nv_bfloat16 h3 = __float2bfloat16(v.w);
    float l0 = v.x - __bfloat162float(h0);
    float l1 = v.y - __bfloat162float(h1);
    float l2 = v.z - __bfloat162float(h2);
    float l3 = v.w - __bfloat162float(h3);
    uint32_t s = sw128(off);
    *(uint2*)(hiBase + s) = make_uint2(pack2(h0, h1), pack2(h2, h3));
    *(uint2*)(loBase + s) = make_uint2(pack2(__float2bfloat16(l0), __float2bfloat16(l1)),
                                       pack2(__float2bfloat16(l2), __float2bfloat16(l3)));
}

// ---------------------------------------------------------------------------
// Device-wide epoch barrier (graph-replay safe). 128 CTAs, all resident.
// ---------------------------------------------------------------------------
__device__ unsigned g_count;
__device__ unsigned g_epoch;

__device__ __forceinline__ void grid_bar() {
    __threadfence();
    __syncthreads();
    if (threadIdx.x == 0) {
        unsigned e;
        asm volatile("ld.acquire.gpu.u32 %0, [%1];" : "=r"(e) : "l"(&g_epoch));
        unsigned prev;
        asm volatile("atom.add.release.gpu.u32 %0, [%1], 1;"
                     : "=r"(prev) : "l"(&g_count));
        if (prev == NBLOCKS - 1) {
            asm volatile("st.relaxed.gpu.u32 [%0], %1;" :: "l"(&g_count), "r"(0u));
            asm volatile("st.release.gpu.u32 [%0], %1;" :: "l"(&g_epoch), "r"(e + 1));
        } else {
            unsigned cur;
            do {
                __nanosleep(32);
                asm volatile("ld.acquire.gpu.u32 %0, [%1];" : "=r"(cur) : "l"(&g_epoch));
            } while (cur == e);
        }
    }
    __syncthreads();
}

// ---------------------------------------------------------------------------
// Phase 1: xp[m,n] = x[m,:] . Wx[n,:] + bx[n]   (3-term bf16 HMMA; unchanged)
// ---------------------------------------------------------------------------
__global__ void __launch_bounds__(256, 1) gemm_xp_kernel(
    const float* __restrict__ A, const float* __restrict__ W,
    const float* __restrict__ bias, float* __restrict__ C)
{
    __shared__ __align__(1024) char sAh[128 * 128];
    __shared__ __align__(1024) char sAl[128 * 128];
    __shared__ __align__(1024) char sBh[64 * 128];
    __shared__ __align__(1024) char sBl[64 * 128];

    const int tid = threadIdx.x;
    const int wid = tid >> 5, lane = tid & 31;
    const int m0 = blockIdx.y * 128;
    const int n0 = blockIdx.x * 64;
    const int wm = (wid >> 1) * 32;
    const int wn = (wid & 1) * 32;

    const uint32_t uAh = smem_u32(sAh), uAl = smem_u32(sAl);
    const uint32_t uBh = smem_u32(sBh), uBl = smem_u32(sBl);

    const int ar = tid >> 4;
    const int ac = tid & 15;
    const float4* __restrict__ A4 = (const float4*)A;
    const float4* __restrict__ W4 = (const float4*)W;

    float c[2][4][4] = {};
    float4 pa[8], pb[4];

    #pragma unroll
    for (int p = 0; p < 8; p++)
        pa[p] = A4[(size_t)(m0 + ar + p * 16) * 256 + ac];
    #pragma unroll
    for (int p = 0; p < 4; p++)
        pb[p] = W4[(size_t)(n0 + ar + p * 16) * 256 + ac];

    for (int ch = 0; ch < 16; ch++) {
        if (ch > 0) __syncthreads();
        #pragma unroll
        for (int p = 0; p < 8; p++)
            split_store(pa[p], sAh, sAl, (uint32_t)((ar + p * 16) * 128 + ac * 8));
        #pragma unroll
        for (int p = 0; p < 4; p++)
            split_store(pb[p], sBh, sBl, (uint32_t)((ar + p * 16) * 128 + ac * 8));
        __syncthreads();

        if (ch < 15) {
            const int kc = (ch + 1) * 16;
            #pragma unroll
            for (int p = 0; p < 8; p++)
                pa[p] = A4[(size_t)(m0 + ar + p * 16) * 256 + kc + ac];
            #pragma unroll
            for (int p = 0; p < 4; p++)
                pb[p] = W4[(size_t)(n0 + ar + p * 16) * 256 + kc + ac];
        }

        #pragma unroll
        for (int ks = 0; ks < 4; ks++) {
            const int q = lane >> 3;
            uint32_t ah[2][4], al[2][4];
            #pragma unroll
            for (int mi = 0; mi < 2; mi++) {
                uint32_t r = (uint32_t)(wm + mi * 16 + (lane & 7) + (q & 1) * 8);
                uint32_t kb = (uint32_t)(ks * 32 + (q >> 1) * 16);
                uint32_t so = sw128(r * 128 + kb);
                ldsm4(ah[mi], uAh + so);
                ldsm4(al[mi], uAl + so);
            }
            uint32_t bhf[2][4], blf[2][4];
            #pragma unroll
            for (int g = 0; g < 2; g++) {
                uint32_t rn = (uint32_t)(wn + g * 16 + (lane & 7) + (q >> 1) * 8);
                uint32_t kb = (uint32_t)(ks * 32 + (q & 1) * 16);
                uint32_t so = sw128(rn * 128 + kb);
                ldsm4(bhf[g], uBh + so);
                ldsm4(blf[g], uBl + so);
            }
            #pragma unroll
            for (int mi = 0; mi < 2; mi++)
                #pragma unroll
                for (int ni = 0; ni < 4; ni++) {
                    uint32_t b0h = bhf[ni >> 1][(ni & 1) * 2];
                    uint32_t b1h = bhf[ni >> 1][(ni & 1) * 2 + 1];
                    uint32_t b0l = blf[ni >> 1][(ni & 1) * 2];
                    uint32_t b1l = blf[ni >> 1][(ni & 1) * 2 + 1];
                    mma_bf16(c[mi][ni], ah[mi], b0h, b1h);
                    mma_bf16(c[mi][ni], ah[mi], b0l, b1l);
                    mma_bf16(c[mi][ni], al[mi], b0h, b1h);
                }
        }
    }

    const int t4 = lane >> 2, cp = (lane & 3) * 2;
    #pragma unroll
    for (int mi = 0; mi < 2; mi++) {
        #pragma unroll
        for (int ni = 0; ni < 4; ni++) {
            const int col = n0 + wn + ni * 8 + cp;
            float2 bv = *(const float2*)&bias[col];
            const int r0 = m0 + wm + mi * 16 + t4;
            float2 v0 = make_float2(c[mi][ni][0] + bv.x, c[mi][ni][1] + bv.y);
            float2 v1 = make_float2(c[mi][ni][2] + bv.x, c[mi][ni][3] + bv.y);
            *(float2*)&C[(size_t)r0 * H_ + col] = v0;
            *(float2*)&C[(size_t)(r0 + 8) * H_ + col] = v1;
        }
    }
}

// ---------------------------------------------------------------------------
// Phase 2: persistent scan. Grid (32, 4) = 128 CTAs, 256 threads.
// Warps 0-3: MMA consumers (CTA tile M=64 x N=32).
// Warps 4-7: producers — pure uint4 copies of pre-split, pre-swizzled h blobs.
// 8 stages/step (128 k per stage = 2 x 64k subchunks), double buffered.
// Epilogue writes h as fp32 (output) AND as bf16 hi/lo swizzled blobs.
// ---------------------------------------------------------------------------
__global__ void __launch_bounds__(256, 1) rnn_scan_kernel(
    const float* __restrict__ Wh, const float* __restrict__ bh,
    float* __restrict__ hall, float* __restrict__ hfinal)
{
    extern __shared__ __align__(1024) char smem[];

    const int tid = threadIdx.x;
    const int wid = tid >> 5, lane = tid & 31;
    const int bx = blockIdx.x;           // n-tile 0..31
    const int by = blockIdx.y;           // m-tile 0..3
    const int n0 = bx * 32;
    const int m0 = by * 64;

    const uint32_t uWhh = smem_u32(smem + OFF_WHH);
    const uint32_t uWhl = smem_u32(smem + OFF_WHL);
    const uint32_t uA   = smem_u32(smem + OFF_ABUF);

    // ---- one-time: split Wh tile into resident SMEM (16 chunks of 32x64) ----
    {
        const float4* __restrict__ W4 = (const float4*)Wh;
        for (int i = tid; i < 8192; i += 256) {
            int r  = i >> 8;
            int f4 = i & 255;
            int c  = f4 >> 4;
            int fc = f4 & 15;
            float4 v = W4[(size_t)(n0 + r) * 256 + f4];
            split_store(v, smem + OFF_WHH + c * 4096, smem + OFF_WHL + c * 4096,
                        (uint32_t)(r * 128 + fc * 8));
        }
    }
    __syncthreads();

    // consumer constants
    const int t4 = lane >> 2, cp = (lane & 3) * 2;
    const int wm = (wid >> 1) * 32;
    const int wn = (wid & 1) * 16;
    float2 bv[2];
    if (wid < 4) {
        bv[0] = *(const float2*)&bh[n0 + wn + 0 + cp];
        bv[1] = *(const float2*)&bh[n0 + wn + 8 + cp];
    }
    // epilogue blob targets for this CTA
    const int sc_w = bx >> 1;                 // subchunk written
    const int colbase = (bx & 1) * 32;        // col offset within 64k tile

    // producer constants
    const int tid2 = tid & 127;

    for (int t = 0; t < TSTEPS; t++) {
        float c[2][2][4] = {};
        float* __restrict__ xp = hall + (size_t)t * BH_;

        // prefetch xp for epilogue (consumers) — hidden under MMA work
        float2 xv[2][2][2];
        if (wid < 4) {
            #pragma unroll
            for (int mi = 0; mi < 2; mi++)
                #pragma unroll
                for (int ni = 0; ni < 2; ni++)
                    #pragma unroll
                    for (int h = 0; h < 2; h++) {
                        const int r = m0 + wm + mi * 16 + t4 + h * 8;
                        const int col = n0 + wn + ni * 8 + cp;
                        xv[mi][ni][h] = *(const float2*)&xp[(size_t)r * H_ + col];
                    }
        }

        if (t > 0) {
            // base of previous h blobs for this m-tile (as uint4)
            const uint4* __restrict__ src =
                (const uint4*)g_hb[(t - 1) & 1][by][0][0];
            // tile stride in uint4: 4096 bf16 = 8192B = 512 uint4
            uint4 pa[16];
            if (wid >= 4) {
                #pragma unroll
                for (int u = 0; u < 16; u++) {
                    int sub = u >> 3, comp = (u >> 2) & 1, p = u & 3;
                    pa[u] = src[(size_t)((0 + sub) * 2 + comp) * 512 + tid2 + p * 128];
                }
            }
            for (int s = 0; s < 8; s++) {
                if (wid >= 4) {
                    char* buf = smem + OFF_ABUF + (s & 1) * STAGE_STRIDE;
                    #pragma unroll
                    for (int u = 0; u < 16; u++) {
                        int sub = u >> 3, comp = (u >> 2) & 1, p = u & 3;
                        *(uint4*)(buf + sub * 16384 + comp * 8192 +
                                  (tid2 + p * 128) * 16) = pa[u];
                    }
                    if (s < 7) {
                        #pragma unroll
                        for (int u = 0; u < 16; u++) {
                            int sub = u >> 3, comp = (u >> 2) & 1, p = u & 3;
                            pa[u] = src[(size_t)(((s + 1) * 2 + sub) * 2 + comp) * 512
                                        + tid2 + p * 128];
                        }
                    }
                }
                __syncthreads();
                if (wid < 4) {
                    const uint32_t uSt = uA + (s & 1) * STAGE_STRIDE;
                    #pragma unroll
                    for (int sub = 0; sub < 2; sub++) {
                        const uint32_t uAb = uSt + sub * 16384;
                        const int ch = s * 2 + sub;
                        #pragma unroll
                        for (int ks = 0; ks < 4; ks++) {
                            const int q = lane >> 3;
                            uint32_t ah[2][4], al[2][4];
                            #pragma unroll
                            for (int mi = 0; mi < 2; mi++) {
                                uint32_t r = (uint32_t)(wm + mi * 16 + (lane & 7) + (q & 1) * 8);
                                uint32_t kb = (uint32_t)(ks * 32 + (q >> 1) * 16);
                                uint32_t so = sw128(r * 128 + kb);
                                ldsm4(ah[mi], uAb + so);
                                ldsm4(al[mi], uAb + 8192 + so);
                            }
                            uint32_t bhf[4], blf[4];
                            {
                                uint32_t rn = (uint32_t)(wn + (lane & 7) + (q >> 1) * 8);
                                uint32_t kb = (uint32_t)(ks * 32 + (q & 1) * 16);
                                uint32_t so = sw128(rn * 128 + kb);
                                ldsm4(bhf, uWhh + ch * 4096 + so);
                                ldsm4(blf, uWhl + ch * 4096 + so);
                            }
                            #pragma unroll
                            for (int mi = 0; mi < 2; mi++)
                                #pragma unroll
                                for (int ni = 0; ni < 2; ni++) {
                                    uint32_t b0h = bhf[ni * 2], b1h = bhf[ni * 2 + 1];
                                    uint32_t b0l = blf[ni * 2], b1l = blf[ni * 2 + 1];
                                    mma_bf16(c[mi][ni], ah[mi], b0h, b1h);
                                    mma_bf16(c[mi][ni], ah[mi], b0l, b1l);
                                    mma_bf16(c[mi][ni], al[mi], b0h, b1h);
                                }
                        }
                    }
                }
            }
        }

        // ---- epilogue (consumers): h = tanh(C + xp + bh); store fp32 + blobs ----
        if (wid < 4) {
            char* dst_hi = (char*)g_hb[t & 1][by][sc_w][0];
            char* dst_lo = (char*)g_hb[t & 1][by][sc_w][1];
            #pragma unroll
            for (int mi = 0; mi < 2; mi++) {
                #pragma unroll
                for (int ni = 0; ni < 2; ni++) {
                    const int col = n0 + wn + ni * 8 + cp;
                    #pragma unroll
                    for (int h = 0; h < 2; h++) {
                        const int r = m0 + wm + mi * 16 + t4 + h * 8;
                        float v0 = tanhf(c[mi][ni][h * 2]     + xv[mi][ni][h].x + bv[ni].x);
                        float v1 = tanhf(c[mi][ni][h * 2 + 1] + xv[mi][ni][h].y + bv[ni].y);
                        *(float2*)&xp[(size_t)r * H_ + col] = make_float2(v0, v1);
                        if (t == TSTEPS - 1)
                            *(float2*)&hfinal[(size_t)r * H_ + col] = make_float2(v0, v1);
                        // split + swizzled blob store (local row, local col)
                        __nv_bfloat16 h0 = __float2bfloat16(v0);
                        __nv_bfloat16 h1 = __float2bfloat16(v1);
                        __nv_bfloat16 l0 = __float2bfloat16(v0 - __bfloat162float(h0));
                        __nv_bfloat16 l1 = __float2bfloat16(v1 - __bfloat162float(h1));
                        const int lr = wm + mi * 16 + t4 + h * 8;          // 0..63
                        const int lc = colbase + wn + ni * 8 + cp;         // 0..63
                        uint32_t off = sw128((uint32_t)(lr * 128 + lc * 2));
                        *(uint32_t*)(dst_hi + off) = pack2(h0, h1);
                        *(uint32_t*)(dst_lo + off) = pack2(l0, l1);
                    }
                }
            }
        }

        if (t < TSTEPS - 1) grid_bar();
    }
}

// ---------------------------------------------------------------------------
// kernel_launch
// ---------------------------------------------------------------------------
extern "C" void kernel_launch(void* const* d_in, const int* in_sizes, int n_in,
                              void* d_out, int out_size)
{
    const float* x  = (const float*)d_in[0];
    const float* Wx = (const float*)d_in[1];
    const float* bx = (const float*)d_in[2];
    const float* Wh = (const float*)d_in[3];
    const float* bh = (const float*)d_in[4];

    float* out    = (float*)d_out;
    float* hfinal = out;                 // [B_ * H_]
    float* hall   = out + BH_;           // [TSTEPS * B_ * H_]

    static int smem_set = 0;
    if (!smem_set) {
        cudaFuncSetAttribute(rnn_scan_kernel,
                             cudaFuncAttributeMaxDynamicSharedMemorySize,
                             SMEM_TOTAL);
        smem_set = 1;
    }

    // Phase 1: xp for all timesteps
    gemm_xp_kernel<<<dim3(16, 1024), 256>>>(x, Wx, bx, hall);

    // Phase 2: persistent tensor-core scan (128 CTAs, all resident)
    rnn_scan_kernel<<<dim3(32, 4), 256, SMEM_TOTAL>>>(Wh, bh, hall, hfinal);
}

// round 6
// speedup vs baseline: 3.9025x; 1.1276x over previous
#include <cuda_runtime.h>
#include <cuda_bf16.h>
#include <stdint.h>
#include <math.h>

// Problem constants
#define TSTEPS 512
#define B_ 256
#define H_ 1024
#define K_ 1024
#define BH_ (B_ * H_)

// Persistent-kernel SMEM map (dynamic)
// Wh hi: 16 chunks x 4KB, Wh lo: same. A: 3 slots x 32KB
// slot = 2 subchunks x {hi 8KB, lo 8KB}
#define OFF_WHH  0
#define OFF_WHL  65536
#define OFF_ABUF 131072
#define SLOT_STRIDE 32768
#define SMEM_TOTAL 229376     // 224 KB -> 1 CTA/SM

// h as pre-swizzled bf16 hi/lo blobs: [parity][mtile][chunk][comp][64r x 64k]
__device__ __nv_bfloat16 g_hb[2][4][16][2][4096];
// per-m-tile monotonic arrival counters (padded to separate cache lines)
__device__ unsigned g_done[4 * 32];

// ---------------------------------------------------------------------------
// Helpers
// ---------------------------------------------------------------------------
__device__ __forceinline__ uint32_t smem_u32(const void* p) {
    uint32_t a;
    asm("{ .reg .u64 t; cvta.to.shared.u64 t, %1; cvt.u32.u64 %0, t; }"
        : "=r"(a) : "l"(p));
    return a;
}
__device__ __forceinline__ uint32_t sw128(uint32_t off) {
    return off ^ ((off >> 3) & 0x70);
}
__device__ __forceinline__ void ldsm4(uint32_t r[4], uint32_t addr) {
    asm volatile("ldmatrix.sync.aligned.m8n8.x4.shared.b16 {%0,%1,%2,%3}, [%4];"
                 : "=r"(r[0]), "=r"(r[1]), "=r"(r[2]), "=r"(r[3]) : "r"(addr));
}
__device__ __forceinline__ void mma_bf16(float c[4], const uint32_t a[4],
                                         uint32_t b0, uint32_t b1) {
    asm volatile(
        "mma.sync.aligned.m16n8k16.row.col.f32.bf16.bf16.f32 "
        "{%0,%1,%2,%3}, {%4,%5,%6,%7}, {%8,%9}, {%0,%1,%2,%3};"
        : "+f"(c[0]), "+f"(c[1]), "+f"(c[2]), "+f"(c[3])
        : "r"(a[0]), "r"(a[1]), "r"(a[2]), "r"(a[3]), "r"(b0), "r"(b1));
}
__device__ __forceinline__ uint32_t pack2(__nv_bfloat16 a, __nv_bfloat16 b) {
    return ((uint32_t)__bfloat16_as_ushort(b) << 16) | __bfloat16_as_ushort(a);
}
__device__ __forceinline__ void split_store(float4 v, char* hiBase, char* loBase,
                                            uint32_t off) {
    __nv_bfloat16 h0 = __float2bfloat16(v.x);
    __nv_bfloat16 h1 = __float2bfloat16(v.y);
    __nv_bfloat16 h2 = __float2bfloat16(v.z);
    __nv_bfloat16 h3 = __float2bfloat16(v.w);
    float l0 = v.x - __bfloat162float(h0);
    float l1 = v.y - __bfloat162float(h1);
    float l2 = v.z - __bfloat162float(h2);
    float l3 = v.w - __bfloat162float(h3);
    uint32_t s = sw128(off);
    *(uint2*)(hiBase + s) = make_uint2(pack2(h0, h1), pack2(h2, h3));
    *(uint2*)(loBase + s) = make_uint2(pack2(__float2bfloat16(l0), __float2bfloat16(l1)),
                                       pack2(__float2bfloat16(l2), __float2bfloat16(l3)));
}
__device__ __forceinline__ void cp16(uint32_t dst, const void* src) {
    asm volatile("cp.async.cg.shared.global [%0], [%1], 16;"
                 :: "r"(dst), "l"(src) : "memory");
}
#define CP_COMMIT() asm volatile("cp.async.commit_group;" ::: "memory")
#define CP_WAIT1()  asm volatile("cp.async.wait_group 1;" ::: "memory")

// ---------------------------------------------------------------------------
// Zero the per-group counters (must run every call before the scan)
// ---------------------------------------------------------------------------
__global__ void zero_flags_kernel() {
    if (threadIdx.x < 4 * 32) g_done[threadIdx.x] = 0;
}

// ---------------------------------------------------------------------------
// Phase 1: xp[m,n] = x[m,:] . Wx[n,:] + bx[n]   (3-term bf16 HMMA; unchanged)
// ---------------------------------------------------------------------------
__global__ void __launch_bounds__(256, 1) gemm_xp_kernel(
    const float* __restrict__ A, const float* __restrict__ W,
    const float* __restrict__ bias, float* __restrict__ C)
{
    __shared__ __align__(1024) char sAh[128 * 128];
    __shared__ __align__(1024) char sAl[128 * 128];
    __shared__ __align__(1024) char sBh[64 * 128];
    __shared__ __align__(1024) char sBl[64 * 128];

    const int tid = threadIdx.x;
    const int wid = tid >> 5, lane = tid & 31;
    const int m0 = blockIdx.y * 128;
    const int n0 = blockIdx.x * 64;
    const int wm = (wid >> 1) * 32;
    const int wn = (wid & 1) * 32;

    const uint32_t uAh = smem_u32(sAh), uAl = smem_u32(sAl);
    const uint32_t uBh = smem_u32(sBh), uBl = smem_u32(sBl);

    const int ar = tid >> 4;
    const int ac = tid & 15;
    const float4* __restrict__ A4 = (const float4*)A;
    const float4* __restrict__ W4 = (const float4*)W;

    float c[2][4][4] = {};
    float4 pa[8], pb[4];

    #pragma unroll
    for (int p = 0; p < 8; p++)
        pa[p] = A4[(size_t)(m0 + ar + p * 16) * 256 + ac];
    #pragma unroll
    for (int p = 0; p < 4; p++)
        pb[p] = W4[(size_t)(n0 + ar + p * 16) * 256 + ac];

    for (int ch = 0; ch < 16; ch++) {
        if (ch > 0) __syncthreads();
        #pragma unroll
        for (int p = 0; p < 8; p++)
            split_store(pa[p], sAh, sAl, (uint32_t)((ar + p * 16) * 128 + ac * 8));
        #pragma unroll
        for (int p = 0; p < 4; p++)
            split_store(pb[p], sBh, sBl, (uint32_t)((ar + p * 16) * 128 + ac * 8));
        __syncthreads();

        if (ch < 15) {
            const int kc = (ch + 1) * 16;
            #pragma unroll
            for (int p = 0; p < 8; p++)
                pa[p] = A4[(size_t)(m0 + ar + p * 16) * 256 + kc + ac];
            #pragma unroll
            for (int p = 0; p < 4; p++)
                pb[p] = W4[(size_t)(n0 + ar + p * 16) * 256 + kc + ac];
        }

        #pragma unroll
        for (int ks = 0; ks < 4; ks++) {
            const int q = lane >> 3;
            uint32_t ah[2][4], al[2][4];
            #pragma unroll
            for (int mi = 0; mi < 2; mi++) {
                uint32_t r = (uint32_t)(wm + mi * 16 + (lane & 7) + (q & 1) * 8);
                uint32_t kb = (uint32_t)(ks * 32 + (q >> 1) * 16);
                uint32_t so = sw128(r * 128 + kb);
                ldsm4(ah[mi], uAh + so);
                ldsm4(al[mi], uAl + so);
            }
            uint32_t bhf[2][4], blf[2][4];
            #pragma unroll
            for (int g = 0; g < 2; g++) {
                uint32_t rn = (uint32_t)(wn + g * 16 + (lane & 7) + (q >> 1) * 8);
                uint32_t kb = (uint32_t)(ks * 32 + (q & 1) * 16);
                uint32_t so = sw128(rn * 128 + kb);
                ldsm4(bhf[g], uBh + so);
                ldsm4(blf[g], uBl + so);
            }
            #pragma unroll
            for (int mi = 0; mi < 2; mi++)
                #pragma unroll
                for (int ni = 0; ni < 4; ni++) {
                    uint32_t b0h = bhf[ni >> 1][(ni & 1) * 2];
                    uint32_t b1h = bhf[ni >> 1][(ni & 1) * 2 + 1];
                    uint32_t b0l = blf[ni >> 1][(ni & 1) * 2];
                    uint32_t b1l = blf[ni >> 1][(ni & 1) * 2 + 1];
                    mma_bf16(c[mi][ni], ah[mi], b0h, b1h);
                    mma_bf16(c[mi][ni], ah[mi], b0l, b1l);
                    mma_bf16(c[mi][ni], al[mi], b0h, b1h);
                }
        }
    }

    const int t4 = lane >> 2, cp = (lane & 3) * 2;
    #pragma unroll
    for (int mi = 0; mi < 2; mi++) {
        #pragma unroll
        for (int ni = 0; ni < 4; ni++) {
            const int col = n0 + wn + ni * 8 + cp;
            float2 bv = *(const float2*)&bias[col];
            const int r0 = m0 + wm + mi * 16 + t4;
            float2 v0 = make_float2(c[mi][ni][0] + bv.x, c[mi][ni][1] + bv.y);
            float2 v1 = make_float2(c[mi][ni][2] + bv.x, c[mi][ni][3] + bv.y);
            *(float2*)&C[(size_t)r0 * H_ + col] = v0;
            *(float2*)&C[(size_t)(r0 + 8) * H_ + col] = v1;
        }
    }
}

// ---------------------------------------------------------------------------
// Phase 2: persistent scan. Grid (32, 4) = 128 CTAs, 256 threads.
// ALL 8 warps compute (warp tile 16x16); A staged via cp.async (3 slots,
// depth 2). Per-m-tile monotonic counter barrier (4 independent groups).
// ---------------------------------------------------------------------------
__global__ void __launch_bounds__(256, 1) rnn_scan_kernel(
    const float* __restrict__ Wh, const float* __restrict__ bh,
    float* __restrict__ hall, float* __restrict__ hfinal)
{
    extern __shared__ __align__(1024) char smem[];

    const int tid = threadIdx.x;
    const int wid = tid >> 5, lane = tid & 31;
    const int bx = blockIdx.x;           // n-tile 0..31
    const int by = blockIdx.y;           // m-tile 0..3
    const int n0 = bx * 32;
    const int m0 = by * 64;

    const uint32_t uWhh = smem_u32(smem + OFF_WHH);
    const uint32_t uWhl = smem_u32(smem + OFF_WHL);
    const uint32_t uA   = smem_u32(smem + OFF_ABUF);

    // ---- one-time: split Wh tile into resident SMEM (16 chunks of 32x64) ----
    {
        const float4* __restrict__ W4 = (const float4*)Wh;
        for (int i = tid; i < 8192; i += 256) {
            int r  = i >> 8;
            int f4 = i & 255;
            int c  = f4 >> 4;
            int fc = f4 & 15;
            float4 v = W4[(size_t)(n0 + r) * 256 + f4];
            split_store(v, smem + OFF_WHH + c * 4096, smem + OFF_WHL + c * 4096,
                        (uint32_t)(r * 128 + fc * 8));
        }
    }
    __syncthreads();

    // warp mapping: 8 warps = 4m x 2n, warp tile 16x16
    const int wm = (wid >> 1) * 16;      // 0,16,32,48
    const int wn = (wid & 1) * 16;       // 0,16
    const int t4 = lane >> 2, cp = (lane & 3) * 2;
    float2 bv[2];
    bv[0] = *(const float2*)&bh[n0 + wn + 0 + cp];
    bv[1] = *(const float2*)&bh[n0 + wn + 8 + cp];

    // epilogue blob targets for this CTA
    const int sc_w = bx >> 1;                 // chunk written
    const int colbase = (bx & 1) * 32;        // col offset within 64k tile

    // cp.async granule mapping: per stage 2048 granules of 16B
    //   g = tid + i*256 (i<8): sub = g>>10, comp = (g>>9)&1, off = (g&511)*16
    unsigned* donep = &g_done[by * 32];

    for (int t = 0; t < TSTEPS; t++) {
        float c[2][4] = {};                   // [ni][reg]
        float* __restrict__ xp = hall + (size_t)t * BH_;

        // prefetch xp for epilogue (before barrier wait — independent of h)
        float2 xv[2][2];
        #pragma unroll
        for (int ni = 0; ni < 2; ni++)
            #pragma unroll
            for (int h = 0; h < 2; h++) {
                const int r = m0 + wm + t4 + h * 8;
                const int col = n0 + wn + ni * 8 + cp;
                xv[ni][h] = *(const float2*)&xp[(size_t)r * H_ + col];
            }

        if (t > 0) {
            // group barrier: wait for all 32 CTAs of this m-tile at step t-1
            if (tid == 0) {
                const unsigned tgt = 32u * (unsigned)t;
                unsigned cur;
                do {
                    asm volatile("ld.acquire.gpu.u32 %0, [%1];"
                                 : "=r"(cur) : "l"(donep));
                    if (cur >= tgt) break;
                    __nanosleep(16);
                } while (true);
            }
            __syncthreads();

            const char* __restrict__ src = (const char*)g_hb[(t - 1) & 1][by];

            // issue stages 0,1
            #pragma unroll
            for (int pre = 0; pre < 2; pre++) {
                #pragma unroll
                for (int i = 0; i < 8; i++) {
                    int g = tid + i * 256;
                    int sub = g >> 10, comp = (g >> 9) & 1, off = (g & 511) * 16;
                    cp16(uA + (pre % 3) * SLOT_STRIDE + sub * 16384 + comp * 8192 + off,
                         src + (size_t)((pre * 2 + sub) * 2 + comp) * 8192 + off);
                }
                CP_COMMIT();
            }

            for (int s = 0; s < 8; s++) {
                CP_WAIT1();
                __syncthreads();
                if (s + 2 < 8) {
                    const int st = s + 2;
                    #pragma unroll
                    for (int i = 0; i < 8; i++) {
                        int g = tid + i * 256;
                        int sub = g >> 10, comp = (g >> 9) & 1, off = (g & 511) * 16;
                        cp16(uA + (st % 3) * SLOT_STRIDE + sub * 16384 + comp * 8192 + off,
                             src + (size_t)((st * 2 + sub) * 2 + comp) * 8192 + off);
                    }
                    CP_COMMIT();
                }
                const uint32_t uSt = uA + (s % 3) * SLOT_STRIDE;
                #pragma unroll
                for (int sub = 0; sub < 2; sub++) {
                    const uint32_t uAb = uSt + sub * 16384;
                    const int ch = s * 2 + sub;
                    #pragma unroll
                    for (int ks = 0; ks < 4; ks++) {
                        const int q = lane >> 3;
                        uint32_t ah[4], al[4];
                        {
                            uint32_t r = (uint32_t)(wm + (lane & 7) + (q & 1) * 8);
                            uint32_t kb = (uint32_t)(ks * 32 + (q >> 1) * 16);
                            uint32_t so = sw128(r * 128 + kb);
                            ldsm4(ah, uAb + so);
                            ldsm4(al, uAb + 8192 + so);
                        }
                        uint32_t bhf[4], blf[4];
                        {
                            uint32_t rn = (uint32_t)(wn + (lane & 7) + (q >> 1) * 8);
                            uint32_t kb = (uint32_t)(ks * 32 + (q & 1) * 16);
                            uint32_t so = sw128(rn * 128 + kb);
                            ldsm4(bhf, uWhh + ch * 4096 + so);
                            ldsm4(blf, uWhl + ch * 4096 + so);
                        }
                        #pragma unroll
                        for (int ni = 0; ni < 2; ni++) {
                            uint32_t b0h = bhf[ni * 2], b1h = bhf[ni * 2 + 1];
                            uint32_t b0l = blf[ni * 2], b1l = blf[ni * 2 + 1];
                            mma_bf16(c[ni], ah, b0h, b1h);
                            mma_bf16(c[ni], ah, b0l, b1l);
                            mma_bf16(c[ni], al, b0h, b1h);
                        }
                    }
                }
            }
        }

        // ---- epilogue: h = tanh(C + xp + bh); store fp32 + bf16 blobs ----
        {
            char* dst_hi = (char*)g_hb[t & 1][by][sc_w][0];
            char* dst_lo = (char*)g_hb[t & 1][by][sc_w][1];
            #pragma unroll
            for (int ni = 0; ni < 2; ni++) {
                const int col = n0 + wn + ni * 8 + cp;
                #pragma unroll
                for (int h = 0; h < 2; h++) {
                    const int r = m0 + wm + t4 + h * 8;
                    float v0 = tanhf(c[ni][h * 2]     + xv[ni][h].x + bv[ni].x);
                    float v1 = tanhf(c[ni][h * 2 + 1] + xv[ni][h].y + bv[ni].y);
                    *(float2*)&xp[(size_t)r * H_ + col] = make_float2(v0, v1);
                    if (t == TSTEPS - 1)
                        *(float2*)&hfinal[(size_t)r * H_ + col] = make_float2(v0, v1);
                    __nv_bfloat16 h0 = __float2bfloat16(v0);
                    __nv_bfloat16 h1 = __float2bfloat16(v1);
                    __nv_bfloat16 l0 = __float2bfloat16(v0 - __bfloat162float(h0));
                    __nv_bfloat16 l1 = __float2bfloat16(v1 - __bfloat162float(h1));
                    const int lr = wm + t4 + h * 8;                  // 0..63
                    const int lc = colbase + wn + ni * 8 + cp;       // 0..63
                    uint32_t off = sw128((uint32_t)(lr * 128 + lc * 2));
                    *(uint32_t*)(dst_hi + off) = pack2(h0, h1);
                    *(uint32_t*)(dst_lo + off) = pack2(l0, l1);
                }
            }
        }

        // arrive (release) for this step
        if (t < TSTEPS - 1) {
            __threadfence();
            __syncthreads();
            if (tid == 0)
                asm volatile("red.release.gpu.global.add.u32 [%0], %1;"
                             :: "l"(donep), "r"(1u) : "memory");
        }
    }
}

// ---------------------------------------------------------------------------
// kernel_launch
// ---------------------------------------------------------------------------
extern "C" void kernel_launch(void* const* d_in, const int* in_sizes, int n_in,
                              void* d_out, int out_size)
{
    const float* x  = (const float*)d_in[0];
    const float* Wx = (const float*)d_in[1];
    const float* bx = (const float*)d_in[2];
    const float* Wh = (const float*)d_in[3];
    const float* bh = (const float*)d_in[4];

    float* out    = (float*)d_out;
    float* hfinal = out;                 // [B_ * H_]
    float* hall   = out + BH_;           // [TSTEPS * B_ * H_]

    static int smem_set = 0;
    if (!smem_set) {
        cudaFuncSetAttribute(rnn_scan_kernel,
                             cudaFuncAttributeMaxDynamicSharedMemorySize,
                             SMEM_TOTAL);
        smem_set = 1;
    }

    // reset per-group counters (graph-replay determinism)
    zero_flags_kernel<<<1, 128>>>();

    // Phase 1: xp for all timesteps
    gemm_xp_kernel<<<dim3(16, 1024), 256>>>(x, Wx, bx, hall);

    // Phase 2: persistent tensor-core scan (128 CTAs, all resident)
    rnn_scan_kernel<<<dim3(32, 4), 256, SMEM_TOTAL>>>(Wh, bh, hall, hfinal);
}

// round 7
// speedup vs baseline: 4.5318x; 1.1612x over previous
#include <cuda_runtime.h>
#include <cuda_bf16.h>
#include <cuda_fp16.h>
#include <stdint.h>
#include <math.h>

// Problem constants
#define TSTEPS 512
#define B_ 256
#define H_ 1024
#define K_ 1024
#define BH_ (B_ * H_)

// Persistent-kernel SMEM map (dynamic)
// Wh hi: 16 chunks x 4KB fp16 (32n x 64k). Wh lo: same. = 128KB
// A: 3 slots x 32KB (slot = 4 chunks x 8KB, 64r x 64k fp16 each)
#define OFF_WHH  0
#define OFF_WHL  65536
#define OFF_ABUF 131072
#define SLOT_STRIDE 32768
#define SMEM_TOTAL 229376     // 224 KB -> 1 CTA/SM

// h as pre-swizzled fp16 blobs: [parity][mtile][chunk][64r x 64k]
__device__ __half g_hf[2][4][16][4096];
// per-m-tile monotonic arrival counters (padded)
__device__ unsigned g_done[4 * 32];

// ---------------------------------------------------------------------------
// Helpers
// ---------------------------------------------------------------------------
__device__ __forceinline__ uint32_t smem_u32(const void* p) {
    uint32_t a;
    asm("{ .reg .u64 t; cvta.to.shared.u64 t, %1; cvt.u32.u64 %0, t; }"
        : "=r"(a) : "l"(p));
    return a;
}
__device__ __forceinline__ uint32_t sw128(uint32_t off) {
    return off ^ ((off >> 3) & 0x70);
}
__device__ __forceinline__ void ldsm4(uint32_t r[4], uint32_t addr) {
    asm volatile("ldmatrix.sync.aligned.m8n8.x4.shared.b16 {%0,%1,%2,%3}, [%4];"
                 : "=r"(r[0]), "=r"(r[1]), "=r"(r[2]), "=r"(r[3]) : "r"(addr));
}
__device__ __forceinline__ void mma_bf16(float c[4], const uint32_t a[4],
                                         uint32_t b0, uint32_t b1) {
    asm volatile(
        "mma.sync.aligned.m16n8k16.row.col.f32.bf16.bf16.f32 "
        "{%0,%1,%2,%3}, {%4,%5,%6,%7}, {%8,%9}, {%0,%1,%2,%3};"
        : "+f"(c[0]), "+f"(c[1]), "+f"(c[2]), "+f"(c[3])
        : "r"(a[0]), "r"(a[1]), "r"(a[2]), "r"(a[3]), "r"(b0), "r"(b1));
}
__device__ __forceinline__ void mma_f16(float c[4], const uint32_t a[4],
                                        uint32_t b0, uint32_t b1) {
    asm volatile(
        "mma.sync.aligned.m16n8k16.row.col.f32.f16.f16.f32 "
        "{%0,%1,%2,%3}, {%4,%5,%6,%7}, {%8,%9}, {%0,%1,%2,%3};"
        : "+f"(c[0]), "+f"(c[1]), "+f"(c[2]), "+f"(c[3])
        : "r"(a[0]), "r"(a[1]), "r"(a[2]), "r"(a[3]), "r"(b0), "r"(b1));
}
__device__ __forceinline__ uint32_t pack2bf(__nv_bfloat16 a, __nv_bfloat16 b) {
    return ((uint32_t)__bfloat16_as_ushort(b) << 16) | __bfloat16_as_ushort(a);
}
__device__ __forceinline__ uint32_t pack2h(__half a, __half b) {
    return ((uint32_t)__half_as_ushort(b) << 16) | __half_as_ushort(a);
}
__device__ __forceinline__ void split_store_bf(float4 v, char* hiBase, char* loBase,
                                               uint32_t off) {
    __nv_bfloat16 h0 = __float2bfloat16(v.x);
    __nv_bfloat16 h1 = __float2bfloat16(v.y);
    __nv_bfloat16 h2 = __float2bfloat16(v.z);
    __nv_bfloat16 h3 = __float2bfloat16(v.w);
    float l0 = v.x - __bfloat162float(h0);
    float l1 = v.y - __bfloat162float(h1);
    float l2 = v.z - __bfloat162float(h2);
    float l3 = v.w - __bfloat162float(h3);
    uint32_t s = sw128(off);
    *(uint2*)(hiBase + s) = make_uint2(pack2bf(h0, h1), pack2bf(h2, h3));
    *(uint2*)(loBase + s) = make_uint2(pack2bf(__float2bfloat16(l0), __float2bfloat16(l1)),
                                       pack2bf(__float2bfloat16(l2), __float2bfloat16(l3)));
}
__device__ __forceinline__ void split_store_h(float4 v, char* hiBase, char* loBase,
                                              uint32_t off) {
    __half h0 = __float2half(v.x);
    __half h1 = __float2half(v.y);
    __half h2 = __float2half(v.z);
    __half h3 = __float2half(v.w);
    float l0 = v.x - __half2float(h0);
    float l1 = v.y - __half2float(h1);
    float l2 = v.z - __half2float(h2);
    float l3 = v.w - __half2float(h3);
    uint32_t s = sw128(off);
    *(uint2*)(hiBase + s) = make_uint2(pack2h(h0, h1), pack2h(h2, h3));
    *(uint2*)(loBase + s) = make_uint2(pack2h(__float2half(l0), __float2half(l1)),
                                       pack2h(__float2half(l2), __float2half(l3)));
}
__device__ __forceinline__ void cp16(uint32_t dst, const void* src) {
    asm volatile("cp.async.cg.shared.global [%0], [%1], 16;"
                 :: "r"(dst), "l"(src) : "memory");
}
#define CP_COMMIT() asm volatile("cp.async.commit_group;" ::: "memory")
#define CP_WAIT1()  asm volatile("cp.async.wait_group 1;" ::: "memory")

// ---------------------------------------------------------------------------
// Zero the per-group counters (every call; graph-replay determinism)
// ---------------------------------------------------------------------------
__global__ void zero_flags_kernel() {
    if (threadIdx.x < 4 * 32) g_done[threadIdx.x] = 0;
}

// ---------------------------------------------------------------------------
// Phase 1: xp[m,n] = x[m,:] . Wx[n,:] + bx[n]   (3-term bf16 HMMA; unchanged)
// ---------------------------------------------------------------------------
__global__ void __launch_bounds__(256, 1) gemm_xp_kernel(
    const float* __restrict__ A, const float* __restrict__ W,
    const float* __restrict__ bias, float* __restrict__ C)
{
    __shared__ __align__(1024) char sAh[128 * 128];
    __shared__ __align__(1024) char sAl[128 * 128];
    __shared__ __align__(1024) char sBh[64 * 128];
    __shared__ __align__(1024) char sBl[64 * 128];

    const int tid = threadIdx.x;
    const int wid = tid >> 5, lane = tid & 31;
    const int m0 = blockIdx.y * 128;
    const int n0 = blockIdx.x * 64;
    const int wm = (wid >> 1) * 32;
    const int wn = (wid & 1) * 32;

    const uint32_t uAh = smem_u32(sAh), uAl = smem_u32(sAl);
    const uint32_t uBh = smem_u32(sBh), uBl = smem_u32(sBl);

    const int ar = tid >> 4;
    const int ac = tid & 15;
    const float4* __restrict__ A4 = (const float4*)A;
    const float4* __restrict__ W4 = (const float4*)W;

    float c[2][4][4] = {};
    float4 pa[8], pb[4];

    #pragma unroll
    for (int p = 0; p < 8; p++)
        pa[p] = A4[(size_t)(m0 + ar + p * 16) * 256 + ac];
    #pragma unroll
    for (int p = 0; p < 4; p++)
        pb[p] = W4[(size_t)(n0 + ar + p * 16) * 256 + ac];

    for (int ch = 0; ch < 16; ch++) {
        if (ch > 0) __syncthreads();
        #pragma unroll
        for (int p = 0; p < 8; p++)
            split_store_bf(pa[p], sAh, sAl, (uint32_t)((ar + p * 16) * 128 + ac * 8));
        #pragma unroll
        for (int p = 0; p < 4; p++)
            split_store_bf(pb[p], sBh, sBl, (uint32_t)((ar + p * 16) * 128 + ac * 8));
        __syncthreads();

        if (ch < 15) {
            const int kc = (ch + 1) * 16;
            #pragma unroll
            for (int p = 0; p < 8; p++)
                pa[p] = A4[(size_t)(m0 + ar + p * 16) * 256 + kc + ac];
            #pragma unroll
            for (int p = 0; p < 4; p++)
                pb[p] = W4[(size_t)(n0 + ar + p * 16) * 256 + kc + ac];
        }

        #pragma unroll
        for (int ks = 0; ks < 4; ks++) {
            const int q = lane >> 3;
            uint32_t ah[2][4], al[2][4];
            #pragma unroll
            for (int mi = 0; mi < 2; mi++) {
                uint32_t r = (uint32_t)(wm + mi * 16 + (lane & 7) + (q & 1) * 8);
                uint32_t kb = (uint32_t)(ks * 32 + (q >> 1) * 16);
                uint32_t so = sw128(r * 128 + kb);
                ldsm4(ah[mi], uAh + so);
                ldsm4(al[mi], uAl + so);
            }
            uint32_t bhf[2][4], blf[2][4];
            #pragma unroll
            for (int g = 0; g < 2; g++) {
                uint32_t rn = (uint32_t)(wn + g * 16 + (lane & 7) + (q >> 1) * 8);
                uint32_t kb = (uint32_t)(ks * 32 + (q & 1) * 16);
                uint32_t so = sw128(rn * 128 + kb);
                ldsm4(bhf[g], uBh + so);
                ldsm4(blf[g], uBl + so);
            }
            #pragma unroll
            for (int mi = 0; mi < 2; mi++)
                #pragma unroll
                for (int ni = 0; ni < 4; ni++) {
                    uint32_t b0h = bhf[ni >> 1][(ni & 1) * 2];
                    uint32_t b1h = bhf[ni >> 1][(ni & 1) * 2 + 1];
                    uint32_t b0l = blf[ni >> 1][(ni & 1) * 2];
                    uint32_t b1l = blf[ni >> 1][(ni & 1) * 2 + 1];
                    mma_bf16(c[mi][ni], ah[mi], b0h, b1h);
                    mma_bf16(c[mi][ni], ah[mi], b0l, b1l);
                    mma_bf16(c[mi][ni], al[mi], b0h, b1h);
                }
        }
    }

    const int t4 = lane >> 2, cp = (lane & 3) * 2;
    #pragma unroll
    for (int mi = 0; mi < 2; mi++) {
        #pragma unroll
        for (int ni = 0; ni < 4; ni++) {
            const int col = n0 + wn + ni * 8 + cp;
            float2 bv = *(const float2*)&bias[col];
            const int r0 = m0 + wm + mi * 16 + t4;
            float2 v0 = make_float2(c[mi][ni][0] + bv.x, c[mi][ni][1] + bv.y);
            float2 v1 = make_float2(c[mi][ni][2] + bv.x, c[mi][ni][3] + bv.y);
            *(float2*)&C[(size_t)r0 * H_ + col] = v0;
            *(float2*)&C[(size_t)(r0 + 8) * H_ + col] = v1;
        }
    }
}

// ---------------------------------------------------------------------------
// Phase 2: persistent scan, fp16 2-term scheme.
// Grid (32, 4) = 128 CTAs, 256 threads; all 8 warps compute (warp tile 16x16).
// h: single fp16 blob (pre-swizzled). Wh: fp16 hi+lo resident in SMEM.
// GEMM term: a * (wh + wl) -> 2 MMAs per k-step per ni.
// A staged via cp.async: 4 stages/step of 32KB (4 chunks), 3 slots, depth 2.
// Per-m-tile monotonic counter barrier (4 independent groups of 32 CTAs).
// ---------------------------------------------------------------------------
__global__ void __launch_bounds__(256, 1) rnn_scan_kernel(
    const float* __restrict__ Wh, const float* __restrict__ bh,
    float* __restrict__ hall, float* __restrict__ hfinal)
{
    extern __shared__ __align__(1024) char smem[];

    const int tid = threadIdx.x;
    const int wid = tid >> 5, lane = tid & 31;
    const int bx = blockIdx.x;           // n-tile 0..31
    const int by = blockIdx.y;           // m-tile 0..3
    const int n0 = bx * 32;
    const int m0 = by * 64;

    const uint32_t uWhh = smem_u32(smem + OFF_WHH);
    const uint32_t uWhl = smem_u32(smem + OFF_WHL);
    const uint32_t uA   = smem_u32(smem + OFF_ABUF);

    // ---- one-time: split Wh tile (fp16 hi/lo) into resident SMEM ----
    {
        const float4* __restrict__ W4 = (const float4*)Wh;
        for (int i = tid; i < 8192; i += 256) {
            int r  = i >> 8;          // n row 0..31
            int f4 = i & 255;         // float4 col
            int c  = f4 >> 4;         // chunk 0..15
            int fc = f4 & 15;
            float4 v = W4[(size_t)(n0 + r) * 256 + f4];
            split_store_h(v, smem + OFF_WHH + c * 4096, smem + OFF_WHL + c * 4096,
                          (uint32_t)(r * 128 + fc * 8));
        }
    }
    __syncthreads();

    // warp mapping: 8 warps = 4m x 2n, warp tile 16x16
    const int wm = (wid >> 1) * 16;
    const int wn = (wid & 1) * 16;
    const int t4 = lane >> 2, cp = (lane & 3) * 2;
    float2 bv[2];
    bv[0] = *(const float2*)&bh[n0 + wn + 0 + cp];
    bv[1] = *(const float2*)&bh[n0 + wn + 8 + cp];

    // epilogue blob target for this CTA
    const int sc_w = bx >> 1;                 // chunk written
    const int colbase = (bx & 1) * 32;        // col offset within 64k chunk

    unsigned* donep = &g_done[by * 32];

    for (int t = 0; t < TSTEPS; t++) {
        float c[2][4] = {};                   // [ni][reg]
        float* __restrict__ xp = hall + (size_t)t * BH_;

        // prefetch xp for epilogue (independent of h)
        float2 xv[2][2];
        #pragma unroll
        for (int ni = 0; ni < 2; ni++)
            #pragma unroll
            for (int h = 0; h < 2; h++) {
                const int r = m0 + wm + t4 + h * 8;
                const int col = n0 + wn + ni * 8 + cp;
                xv[ni][h] = *(const float2*)&xp[(size_t)r * H_ + col];
            }

        if (t > 0) {
            // group barrier: all 32 CTAs of this m-tile finished step t-1
            if (tid == 0) {
                const unsigned tgt = 32u * (unsigned)t;
                unsigned cur;
                do {
                    asm volatile("ld.acquire.gpu.u32 %0, [%1];"
                                 : "=r"(cur) : "l"(donep));
                    if (cur >= tgt) break;
                    __nanosleep(16);
                } while (true);
            }
            __syncthreads();

            const char* __restrict__ src = (const char*)g_hf[(t - 1) & 1][by];

            // stage = 4 chunks (8KB each) = 32KB; granule mapping:
            // g = tid + i*256 (i<8): sub = g>>9, off = (g&511)*16
            #pragma unroll
            for (int pre = 0; pre < 2; pre++) {
                #pragma unroll
                for (int i = 0; i < 8; i++) {
                    int g = tid + i * 256;
                    int sub = g >> 9, off = (g & 511) * 16;
                    cp16(uA + (pre % 3) * SLOT_STRIDE + sub * 8192 + off,
                         src + (size_t)(pre * 4 + sub) * 8192 + off);
                }
                CP_COMMIT();
            }

            for (int s = 0; s < 4; s++) {
                CP_WAIT1();
                __syncthreads();
                if (s + 2 < 4) {
                    const int st = s + 2;
                    #pragma unroll
                    for (int i = 0; i < 8; i++) {
                        int g = tid + i * 256;
                        int sub = g >> 9, off = (g & 511) * 16;
                        cp16(uA + (st % 3) * SLOT_STRIDE + sub * 8192 + off,
                             src + (size_t)(st * 4 + sub) * 8192 + off);
                    }
                    CP_COMMIT();
                }
                const uint32_t uSt = uA + (s % 3) * SLOT_STRIDE;
                #pragma unroll
                for (int sub = 0; sub < 4; sub++) {
                    const uint32_t uAb = uSt + sub * 8192;
                    const int ch = s * 4 + sub;
                    #pragma unroll
                    for (int ks = 0; ks < 4; ks++) {
                        const int q = lane >> 3;
                        uint32_t af[4];
                        {
                            uint32_t r = (uint32_t)(wm + (lane & 7) + (q & 1) * 8);
                            uint32_t kb = (uint32_t)(ks * 32 + (q >> 1) * 16);
                            ldsm4(af, uAb + sw128(r * 128 + kb));
                        }
                        uint32_t bhf[4], blf[4];
                        {
                            uint32_t rn = (uint32_t)(wn + (lane & 7) + (q >> 1) * 8);
                            uint32_t kb = (uint32_t)(ks * 32 + (q & 1) * 16);
                            uint32_t so = sw128(rn * 128 + kb);
                            ldsm4(bhf, uWhh + ch * 4096 + so);
                            ldsm4(blf, uWhl + ch * 4096 + so);
                        }
                        #pragma unroll
                        for (int ni = 0; ni < 2; ni++) {
                            mma_f16(c[ni], af, bhf[ni * 2], bhf[ni * 2 + 1]);
                            mma_f16(c[ni], af, blf[ni * 2], blf[ni * 2 + 1]);
                        }
                    }
                }
            }
        }

        // ---- epilogue: h = tanh(C + xp + bh); store fp32 + fp16 blob ----
        {
            char* dst = (char*)g_hf[t & 1][by][sc_w];
            #pragma unroll
            for (int ni = 0; ni < 2; ni++) {
                const int col = n0 + wn + ni * 8 + cp;
                #pragma unroll
                for (int h = 0; h < 2; h++) {
                    const int r = m0 + wm + t4 + h * 8;
                    float v0 = tanhf(c[ni][h * 2]     + xv[ni][h].x + bv[ni].x);
                    float v1 = tanhf(c[ni][h * 2 + 1] + xv[ni][h].y + bv[ni].y);
                    *(float2*)&xp[(size_t)r * H_ + col] = make_float2(v0, v1);
                    if (t == TSTEPS - 1)
                        *(float2*)&hfinal[(size_t)r * H_ + col] = make_float2(v0, v1);
                    const int lr = wm + t4 + h * 8;                  // 0..63
                    const int lc = colbase + wn + ni * 8 + cp;       // 0..63
                    uint32_t off = sw128((uint32_t)(lr * 128 + lc * 2));
                    *(uint32_t*)(dst + off) = pack2h(__float2half(v0), __float2half(v1));
                }
            }
        }

        // arrive (release) for this step
        if (t < TSTEPS - 1) {
            __threadfence();
            __syncthreads();
            if (tid == 0)
                asm volatile("red.release.gpu.global.add.u32 [%0], %1;"
                             :: "l"(donep), "r"(1u) : "memory");
        }
    }
}

// ---------------------------------------------------------------------------
// kernel_launch
// ---------------------------------------------------------------------------
extern "C" void kernel_launch(void* const* d_in, const int* in_sizes, int n_in,
                              void* d_out, int out_size)
{
    const float* x  = (const float*)d_in[0];
    const float* Wx = (const float*)d_in[1];
    const float* bx = (const float*)d_in[2];
    const float* Wh = (const float*)d_in[3];
    const float* bh = (const float*)d_in[4];

    float* out    = (float*)d_out;
    float* hfinal = out;                 // [B_ * H_]
    float* hall   = out + BH_;           // [TSTEPS * B_ * H_]

    static int smem_set = 0;
    if (!smem_set) {
        cudaFuncSetAttribute(rnn_scan_kernel,
                             cudaFuncAttributeMaxDynamicSharedMemorySize,
                             SMEM_TOTAL);
        smem_set = 1;
    }

    // reset per-group counters (graph-replay determinism)
    zero_flags_kernel<<<1, 128>>>();

    // Phase 1: xp for all timesteps
    gemm_xp_kernel<<<dim3(16, 1024), 256>>>(x, Wx, bx, hall);

    // Phase 2: persistent tensor-core scan (128 CTAs, all resident)
    rnn_scan_kernel<<<dim3(32, 4), 256, SMEM_TOTAL>>>(Wh, bh, hall, hfinal);
}

// round 8
// speedup vs baseline: 4.6367x; 1.0232x over previous
#include <cuda_runtime.h>
#include <cuda_bf16.h>
#include <cuda_fp16.h>
#include <stdint.h>
#include <math.h>

// Problem constants
#define TSTEPS 512
#define B_ 256
#define H_ 1024
#define K_ 1024
#define BH_ (B_ * H_)

// Persistent-kernel SMEM map (dynamic)
// Wh: 16 chunks x 4KB fp16 (32n x 64k) = 64KB
// A: 3 slots x 32KB (slot = 4 chunks x 8KB, 64r x 64k fp16)
#define OFF_WH   0
#define OFF_ABUF 65536
#define SLOT_STRIDE 32768
#define SMEM_TOTAL 163840     // 160 KB -> 1 CTA/SM

// h as pre-swizzled fp16 blobs: [parity][mtile][chunk][64r x 64k]
__device__ __half g_hf[2][4][16][4096];
// per-(mtile, stage) monotonic producer flags, padded to 128B lines
__device__ unsigned g_done[4 * 4 * 32];

// ---------------------------------------------------------------------------
// Helpers
// ---------------------------------------------------------------------------
__device__ __forceinline__ uint32_t smem_u32(const void* p) {
    uint32_t a;
    asm("{ .reg .u64 t; cvta.to.shared.u64 t, %1; cvt.u32.u64 %0, t; }"
        : "=r"(a) : "l"(p));
    return a;
}
__device__ __forceinline__ uint32_t sw128(uint32_t off) {
    return off ^ ((off >> 3) & 0x70);
}
__device__ __forceinline__ void ldsm4(uint32_t r[4], uint32_t addr) {
    asm volatile("ldmatrix.sync.aligned.m8n8.x4.shared.b16 {%0,%1,%2,%3}, [%4];"
                 : "=r"(r[0]), "=r"(r[1]), "=r"(r[2]), "=r"(r[3]) : "r"(addr));
}
__device__ __forceinline__ void mma_bf16(float c[4], const uint32_t a[4],
                                         uint32_t b0, uint32_t b1) {
    asm volatile(
        "mma.sync.aligned.m16n8k16.row.col.f32.bf16.bf16.f32 "
        "{%0,%1,%2,%3}, {%4,%5,%6,%7}, {%8,%9}, {%0,%1,%2,%3};"
        : "+f"(c[0]), "+f"(c[1]), "+f"(c[2]), "+f"(c[3])
        : "r"(a[0]), "r"(a[1]), "r"(a[2]), "r"(a[3]), "r"(b0), "r"(b1));
}
__device__ __forceinline__ void mma_f16(float c[4], const uint32_t a[4],
                                        uint32_t b0, uint32_t b1) {
    asm volatile(
        "mma.sync.aligned.m16n8k16.row.col.f32.f16.f16.f32 "
        "{%0,%1,%2,%3}, {%4,%5,%6,%7}, {%8,%9}, {%0,%1,%2,%3};"
        : "+f"(c[0]), "+f"(c[1]), "+f"(c[2]), "+f"(c[3])
        : "r"(a[0]), "r"(a[1]), "r"(a[2]), "r"(a[3]), "r"(b0), "r"(b1));
}
__device__ __forceinline__ uint32_t pack2bf(__nv_bfloat16 a, __nv_bfloat16 b) {
    return ((uint32_t)__bfloat16_as_ushort(b) << 16) | __bfloat16_as_ushort(a);
}
__device__ __forceinline__ uint32_t pack2h(__half a, __half b) {
    return ((uint32_t)__half_as_ushort(b) << 16) | __half_as_ushort(a);
}
__device__ __forceinline__ void split_store_bf(float4 v, char* hiBase, char* loBase,
                                               uint32_t off) {
    __nv_bfloat16 h0 = __float2bfloat16(v.x);
    __nv_bfloat16 h1 = __float2bfloat16(v.y);
    __nv_bfloat16 h2 = __float2bfloat16(v.z);
    __nv_bfloat16 h3 = __float2bfloat16(v.w);
    float l0 = v.x - __bfloat162float(h0);
    float l1 = v.y - __bfloat162float(h1);
    float l2 = v.z - __bfloat162float(h2);
    float l3 = v.w - __bfloat162float(h3);
    uint32_t s = sw128(off);
    *(uint2*)(hiBase + s) = make_uint2(pack2bf(h0, h1), pack2bf(h2, h3));
    *(uint2*)(loBase + s) = make_uint2(pack2bf(__float2bfloat16(l0), __float2bfloat16(l1)),
                                       pack2bf(__float2bfloat16(l2), __float2bfloat16(l3)));
}
__device__ __forceinline__ void round_store_h(float4 v, char* base, uint32_t off) {
    uint32_t s = sw128(off);
    *(uint2*)(base + s) = make_uint2(
        pack2h(__float2half(v.x), __float2half(v.y)),
        pack2h(__float2half(v.z), __float2half(v.w)));
}
__device__ __forceinline__ void cp16(uint32_t dst, const void* src) {
    asm volatile("cp.async.cg.shared.global [%0], [%1], 16;"
                 :: "r"(dst), "l"(src) : "memory");
}
#define CP_COMMIT() asm volatile("cp.async.commit_group;" ::: "memory")
#define CP_WAIT1()  asm volatile("cp.async.wait_group 1;" ::: "memory")

// ---------------------------------------------------------------------------
// Zero flags (every call; graph-replay determinism)
// ---------------------------------------------------------------------------
__global__ void zero_flags_kernel() {
    g_done[threadIdx.x] = 0;   // 512 threads cover 4*4*32
}

// ---------------------------------------------------------------------------
// Phase 1: xp[m,n] = x[m,:] . Wx[n,:] + bx[n]   (3-term bf16 HMMA; unchanged)
// ---------------------------------------------------------------------------
__global__ void __launch_bounds__(256, 1) gemm_xp_kernel(
    const float* __restrict__ A, const float* __restrict__ W,
    const float* __restrict__ bias, float* __restrict__ C)
{
    __shared__ __align__(1024) char sAh[128 * 128];
    __shared__ __align__(1024) char sAl[128 * 128];
    __shared__ __align__(1024) char sBh[64 * 128];
    __shared__ __align__(1024) char sBl[64 * 128];

    const int tid = threadIdx.x;
    const int wid = tid >> 5, lane = tid & 31;
    const int m0 = blockIdx.y * 128;
    const int n0 = blockIdx.x * 64;
    const int wm = (wid >> 1) * 32;
    const int wn = (wid & 1) * 32;

    const uint32_t uAh = smem_u32(sAh), uAl = smem_u32(sAl);
    const uint32_t uBh = smem_u32(sBh), uBl = smem_u32(sBl);

    const int ar = tid >> 4;
    const int ac = tid & 15;
    const float4* __restrict__ A4 = (const float4*)A;
    const float4* __restrict__ W4 = (const float4*)W;

    float c[2][4][4] = {};
    float4 pa[8], pb[4];

    #pragma unroll
    for (int p = 0; p < 8; p++)
        pa[p] = A4[(size_t)(m0 + ar + p * 16) * 256 + ac];
    #pragma unroll
    for (int p = 0; p < 4; p++)
        pb[p] = W4[(size_t)(n0 + ar + p * 16) * 256 + ac];

    for (int ch = 0; ch < 16; ch++) {
        if (ch > 0) __syncthreads();
        #pragma unroll
        for (int p = 0; p < 8; p++)
            split_store_bf(pa[p], sAh, sAl, (uint32_t)((ar + p * 16) * 128 + ac * 8));
        #pragma unroll
        for (int p = 0; p < 4; p++)
            split_store_bf(pb[p], sBh, sBl, (uint32_t)((ar + p * 16) * 128 + ac * 8));
        __syncthreads();

        if (ch < 15) {
            const int kc = (ch + 1) * 16;
            #pragma unroll
            for (int p = 0; p < 8; p++)
                pa[p] = A4[(size_t)(m0 + ar + p * 16) * 256 + kc + ac];
            #pragma unroll
            for (int p = 0; p < 4; p++)
                pb[p] = W4[(size_t)(n0 + ar + p * 16) * 256 + kc + ac];
        }

        #pragma unroll
        for (int ks = 0; ks < 4; ks++) {
            const int q = lane >> 3;
            uint32_t ah[2][4], al[2][4];
            #pragma unroll
            for (int mi = 0; mi < 2; mi++) {
                uint32_t r = (uint32_t)(wm + mi * 16 + (lane & 7) + (q & 1) * 8);
                uint32_t kb = (uint32_t)(ks * 32 + (q >> 1) * 16);
                uint32_t so = sw128(r * 128 + kb);
                ldsm4(ah[mi], uAh + so);
                ldsm4(al[mi], uAl + so);
            }
            uint32_t bhf[2][4], blf[2][4];
            #pragma unroll
            for (int g = 0; g < 2; g++) {
                uint32_t rn = (uint32_t)(wn + g * 16 + (lane & 7) + (q >> 1) * 8);
                uint32_t kb = (uint32_t)(ks * 32 + (q & 1) * 16);
                uint32_t so = sw128(rn * 128 + kb);
                ldsm4(bhf[g], uBh + so);
                ldsm4(blf[g], uBl + so);
            }
            #pragma unroll
            for (int mi = 0; mi < 2; mi++)
                #pragma unroll
                for (int ni = 0; ni < 4; ni++) {
                    uint32_t b0h = bhf[ni >> 1][(ni & 1) * 2];
                    uint32_t b1h = bhf[ni >> 1][(ni & 1) * 2 + 1];
                    uint32_t b0l = blf[ni >> 1][(ni & 1) * 2];
                    uint32_t b1l = blf[ni >> 1][(ni & 1) * 2 + 1];
                    mma_bf16(c[mi][ni], ah[mi], b0h, b1h);
                    mma_bf16(c[mi][ni], ah[mi], b0l, b1l);
                    mma_bf16(c[mi][ni], al[mi], b0h, b1h);
                }
        }
    }

    const int t4 = lane >> 2, cp = (lane & 3) * 2;
    #pragma unroll
    for (int mi = 0; mi < 2; mi++) {
        #pragma unroll
        for (int ni = 0; ni < 4; ni++) {
            const int col = n0 + wn + ni * 8 + cp;
            float2 bv = *(const float2*)&bias[col];
            const int r0 = m0 + wm + mi * 16 + t4;
            float2 v0 = make_float2(c[mi][ni][0] + bv.x, c[mi][ni][1] + bv.y);
            float2 v1 = make_float2(c[mi][ni][2] + bv.x, c[mi][ni][3] + bv.y);
            *(float2*)&C[(size_t)r0 * H_ + col] = v0;
            *(float2*)&C[(size_t)(r0 + 8) * H_ + col] = v1;
        }
    }
}

// ---------------------------------------------------------------------------
// Phase 2: persistent scan, pure fp16 GEMM, per-stage dataflow flags.
// Grid (32, 4) = 128 CTAs, 256 threads; 8 warps compute (warp tile 16x16).
// Flags: flag[by][s] incremented (release) by the 8 CTAs bx in [8s, 8s+8)
// after their step-t epilogue; consumers acquire-poll >= 8*t before issuing
// stage s's cp.async. Completion of a step still implies all 32 producers
// of the previous step are done => 2-parity ping-pong has no WAR hazard.
// ---------------------------------------------------------------------------
__global__ void __launch_bounds__(256, 1) rnn_scan_kernel(
    const float* __restrict__ Wh, const float* __restrict__ bh,
    float* __restrict__ hall, float* __restrict__ hfinal)
{
    extern __shared__ __align__(1024) char smem[];

    const int tid = threadIdx.x;
    const int wid = tid >> 5, lane = tid & 31;
    const int bx = blockIdx.x;           // n-tile 0..31
    const int by = blockIdx.y;           // m-tile 0..3
    const int n0 = bx * 32;
    const int m0 = by * 64;

    const uint32_t uWh = smem_u32(smem + OFF_WH);
    const uint32_t uA  = smem_u32(smem + OFF_ABUF);

    // ---- one-time: round Wh tile to fp16 into resident SMEM ----
    {
        const float4* __restrict__ W4 = (const float4*)Wh;
        for (int i = tid; i < 8192; i += 256) {
            int r  = i >> 8;          // n row 0..31
            int f4 = i & 255;         // float4 col
            int c  = f4 >> 4;         // chunk 0..15
            int fc = f4 & 15;
            float4 v = W4[(size_t)(n0 + r) * 256 + f4];
            round_store_h(v, smem + OFF_WH + c * 4096,
                          (uint32_t)(r * 128 + fc * 8));
        }
    }
    __syncthreads();

    // warp mapping: 8 warps = 4m x 2n, warp tile 16x16
    const int wm = (wid >> 1) * 16;
    const int wn = (wid & 1) * 16;
    const int t4 = lane >> 2, cp = (lane & 3) * 2;
    float2 bv[2];
    bv[0] = *(const float2*)&bh[n0 + wn + 0 + cp];
    bv[1] = *(const float2*)&bh[n0 + wn + 8 + cp];

    // epilogue blob target / flag for this CTA
    const int sc_w = bx >> 1;                 // chunk written
    const int colbase = (bx & 1) * 32;        // col offset within chunk
    unsigned* flags = &g_done[(by * 4) * 32]; // flag[s] at flags[s*32]
    unsigned* myflag = &flags[(bx >> 3) * 32];

    for (int t = 0; t < TSTEPS; t++) {
        float c[2][4] = {};                   // [ni][reg]
        float* __restrict__ xp = hall + (size_t)t * BH_;

        // prefetch xp for epilogue (independent of h)
        float2 xv[2][2];
        #pragma unroll
        for (int ni = 0; ni < 2; ni++)
            #pragma unroll
            for (int h = 0; h < 2; h++) {
                const int r = m0 + wm + t4 + h * 8;
                const int col = n0 + wn + ni * 8 + cp;
                xv[ni][h] = *(const float2*)&xp[(size_t)r * H_ + col];
            }

        if (t > 0) {
            const char* __restrict__ src = (const char*)g_hf[(t - 1) & 1][by];
            const unsigned tgt = 8u * (unsigned)t;

            // issue stages 0,1 (each gated by its producer flag)
            #pragma unroll
            for (int pre = 0; pre < 2; pre++) {
                if (tid == 0) {
                    unsigned cur;
                    do {
                        asm volatile("ld.acquire.gpu.u32 %0, [%1];"
                                     : "=r"(cur) : "l"(&flags[pre * 32]));
                        if (cur >= tgt) break;
                        __nanosleep(16);
                    } while (true);
                }
                __syncthreads();
                #pragma unroll
                for (int i = 0; i < 8; i++) {
                    int g = tid + i * 256;
                    int sub = g >> 9, off = (g & 511) * 16;
                    cp16(uA + (pre % 3) * SLOT_STRIDE + sub * 8192 + off,
                         src + (size_t)(pre * 4 + sub) * 8192 + off);
                }
                CP_COMMIT();
            }

            for (int s = 0; s < 4; s++) {
                CP_WAIT1();
                __syncthreads();
                if (s + 2 < 4) {
                    const int st = s + 2;
                    if (tid == 0) {
                        unsigned cur;
                        do {
                            asm volatile("ld.acquire.gpu.u32 %0, [%1];"
                                         : "=r"(cur) : "l"(&flags[st * 32]));
                            if (cur >= tgt) break;
                            __nanosleep(16);
                        } while (true);
                    }
                    __syncthreads();
                    #pragma unroll
                    for (int i = 0; i < 8; i++) {
                        int g = tid + i * 256;
                        int sub = g >> 9, off = (g & 511) * 16;
                        cp16(uA + (st % 3) * SLOT_STRIDE + sub * 8192 + off,
                             src + (size_t)(st * 4 + sub) * 8192 + off);
                    }
                    CP_COMMIT();
                }
                const uint32_t uSt = uA + (s % 3) * SLOT_STRIDE;
                #pragma unroll
                for (int sub = 0; sub < 4; sub++) {
                    const uint32_t uAb = uSt + sub * 8192;
                    const int ch = s * 4 + sub;
                    #pragma unroll
                    for (int ks = 0; ks < 4; ks++) {
                        const int q = lane >> 3;
                        uint32_t af[4];
                        {
                            uint32_t r = (uint32_t)(wm + (lane & 7) + (q & 1) * 8);
                            uint32_t kb = (uint32_t)(ks * 32 + (q >> 1) * 16);
                            ldsm4(af, uAb + sw128(r * 128 + kb));
                        }
                        uint32_t bf[4];
                        {
                            uint32_t rn = (uint32_t)(wn + (lane & 7) + (q >> 1) * 8);
                            uint32_t kb = (uint32_t)(ks * 32 + (q & 1) * 16);
                            ldsm4(bf, uWh + ch * 4096 + sw128(rn * 128 + kb));
                        }
                        mma_f16(c[0], af, bf[0], bf[1]);
                        mma_f16(c[1], af, bf[2], bf[3]);
                    }
                }
            }
        }

        // ---- epilogue: h = tanh(C + xp + bh); store fp32 + fp16 blob ----
        {
            char* dst = (char*)g_hf[t & 1][by][sc_w];
            #pragma unroll
            for (int ni = 0; ni < 2; ni++) {
                const int col = n0 + wn + ni * 8 + cp;
                #pragma unroll
                for (int h = 0; h < 2; h++) {
                    const int r = m0 + wm + t4 + h * 8;
                    float v0 = tanhf(c[ni][h * 2]     + xv[ni][h].x + bv[ni].x);
                    float v1 = tanhf(c[ni][h * 2 + 1] + xv[ni][h].y + bv[ni].y);
                    *(float2*)&xp[(size_t)r * H_ + col] = make_float2(v0, v1);
                    if (t == TSTEPS - 1)
                        *(float2*)&hfinal[(size_t)r * H_ + col] = make_float2(v0, v1);
                    const int lr = wm + t4 + h * 8;                  // 0..63
                    const int lc = colbase + wn + ni * 8 + cp;       // 0..63
                    uint32_t off = sw128((uint32_t)(lr * 128 + lc * 2));
                    *(uint32_t*)(dst + off) = pack2h(__float2half(v0), __float2half(v1));
                }
            }
        }

        // arrive (release) on this CTA's stage flag
        if (t < TSTEPS - 1) {
            __threadfence();
            __syncthreads();
            if (tid == 0)
                asm volatile("red.release.gpu.global.add.u32 [%0], %1;"
                             :: "l"(myflag), "r"(1u) : "memory");
        }
    }
}

// ---------------------------------------------------------------------------
// kernel_launch
// ---------------------------------------------------------------------------
extern "C" void kernel_launch(void* const* d_in, const int* in_sizes, int n_in,
                              void* d_out, int out_size)
{
    const float* x  = (const float*)d_in[0];
    const float* Wx = (const float*)d_in[1];
    const float* bx = (const float*)d_in[2];
    const float* Wh = (const float*)d_in[3];
    const float* bh = (const float*)d_in[4];

    float* out    = (float*)d_out;
    float* hfinal = out;                 // [B_ * H_]
    float* hall   = out + BH_;           // [TSTEPS * B_ * H_]

    static int smem_set = 0;
    if (!smem_set) {
        cudaFuncSetAttribute(rnn_scan_kernel,
                             cudaFuncAttributeMaxDynamicSharedMemorySize,
                             SMEM_TOTAL);
        smem_set = 1;
    }

    // reset flags (graph-replay determinism)
    zero_flags_kernel<<<1, 512>>>();

    // Phase 1: xp for all timesteps
    gemm_xp_kernel<<<dim3(16, 1024), 256>>>(x, Wx, bx, hall);

    // Phase 2: persistent tensor-core scan (128 CTAs, all resident)
    rnn_scan_kernel<<<dim3(32, 4), 256, SMEM_TOTAL>>>(Wh, bh, hall, hfinal);
}

// round 9
// speedup vs baseline: 5.0684x; 1.0931x over previous
#include <cuda_runtime.h>
#include <cuda_bf16.h>
#include <cuda_fp16.h>
#include <stdint.h>
#include <math.h>

// Problem constants
#define TSTEPS 512
#define B_ 256
#define H_ 1024
#define K_ 1024
#define BH_ (B_ * H_)

// Scan SMEM: Wh resident fp16, 16 chunks x 4KB (32n x 64k each)
#define OFF_WH   0
#define SMEM_TOTAL 65536

// h in mma-A-fragment layout:
// [parity][mtile(4)][rowgrp(4)][kstep(64)][lane(32)] x uint4  = 2MB total
__device__ uint4 g_frag[2][4][4][64][32];
// per-(mtile, stage) monotonic warp-arrival flags (padded to 128B lines)
__device__ unsigned g_done[4 * 4 * 32];

// ---------------------------------------------------------------------------
// Helpers
// ---------------------------------------------------------------------------
__device__ __forceinline__ uint32_t smem_u32(const void* p) {
    uint32_t a;
    asm("{ .reg .u64 t; cvta.to.shared.u64 t, %1; cvt.u32.u64 %0, t; }"
        : "=r"(a) : "l"(p));
    return a;
}
__device__ __forceinline__ uint32_t sw128(uint32_t off) {
    return off ^ ((off >> 3) & 0x70);
}
__device__ __forceinline__ void ldsm4(uint32_t r[4], uint32_t addr) {
    asm volatile("ldmatrix.sync.aligned.m8n8.x4.shared.b16 {%0,%1,%2,%3}, [%4];"
                 : "=r"(r[0]), "=r"(r[1]), "=r"(r[2]), "=r"(r[3]) : "r"(addr));
}
__device__ __forceinline__ void mma_bf16(float c[4], const uint32_t a[4],
                                         uint32_t b0, uint32_t b1) {
    asm volatile(
        "mma.sync.aligned.m16n8k16.row.col.f32.bf16.bf16.f32 "
        "{%0,%1,%2,%3}, {%4,%5,%6,%7}, {%8,%9}, {%0,%1,%2,%3};"
        : "+f"(c[0]), "+f"(c[1]), "+f"(c[2]), "+f"(c[3])
        : "r"(a[0]), "r"(a[1]), "r"(a[2]), "r"(a[3]), "r"(b0), "r"(b1));
}
__device__ __forceinline__ void mma_f16(float c[4], const uint32_t a[4],
                                        uint32_t b0, uint32_t b1) {
    asm volatile(
        "mma.sync.aligned.m16n8k16.row.col.f32.f16.f16.f32 "
        "{%0,%1,%2,%3}, {%4,%5,%6,%7}, {%8,%9}, {%0,%1,%2,%3};"
        : "+f"(c[0]), "+f"(c[1]), "+f"(c[2]), "+f"(c[3])
        : "r"(a[0]), "r"(a[1]), "r"(a[2]), "r"(a[3]), "r"(b0), "r"(b1));
}
__device__ __forceinline__ uint32_t pack2bf(__nv_bfloat16 a, __nv_bfloat16 b) {
    return ((uint32_t)__bfloat16_as_ushort(b) << 16) | __bfloat16_as_ushort(a);
}
__device__ __forceinline__ uint32_t pack2h(__half a, __half b) {
    return ((uint32_t)__half_as_ushort(b) << 16) | __half_as_ushort(a);
}
__device__ __forceinline__ void split_store_bf(float4 v, char* hiBase, char* loBase,
                                               uint32_t off) {
    __nv_bfloat16 h0 = __float2bfloat16(v.x);
    __nv_bfloat16 h1 = __float2bfloat16(v.y);
    __nv_bfloat16 h2 = __float2bfloat16(v.z);
    __nv_bfloat16 h3 = __float2bfloat16(v.w);
    float l0 = v.x - __bfloat162float(h0);
    float l1 = v.y - __bfloat162float(h1);
    float l2 = v.z - __bfloat162float(h2);
    float l3 = v.w - __bfloat162float(h3);
    uint32_t s = sw128(off);
    *(uint2*)(hiBase + s) = make_uint2(pack2bf(h0, h1), pack2bf(h2, h3));
    *(uint2*)(loBase + s) = make_uint2(pack2bf(__float2bfloat16(l0), __float2bfloat16(l1)),
                                       pack2bf(__float2bfloat16(l2), __float2bfloat16(l3)));
}
__device__ __forceinline__ void round_store_h(float4 v, char* base, uint32_t off) {
    uint32_t s = sw128(off);
    *(uint2*)(base + s) = make_uint2(
        pack2h(__float2half(v.x), __float2half(v.y)),
        pack2h(__float2half(v.z), __float2half(v.w)));
}
__device__ __forceinline__ uint4 ldgcg4(const uint4* p) {
    uint4 v;
    asm volatile("ld.global.cg.v4.u32 {%0,%1,%2,%3}, [%4];"
                 : "=r"(v.x), "=r"(v.y), "=r"(v.z), "=r"(v.w) : "l"(p));
    return v;
}
__device__ __forceinline__ void stg4(uint4* p, uint4 v) {
    asm volatile("st.global.v4.u32 [%0], {%1,%2,%3,%4};"
                 :: "l"(p), "r"(v.x), "r"(v.y), "r"(v.z), "r"(v.w) : "memory");
}

// ---------------------------------------------------------------------------
// Zero flags (every call; graph-replay determinism)
// ---------------------------------------------------------------------------
__global__ void zero_flags_kernel() {
    g_done[threadIdx.x] = 0;   // 512 threads cover 4*4*32
}

// ---------------------------------------------------------------------------
// Phase 1: xp[m,n] = x[m,:] . Wx[n,:] + bx[n]   (3-term bf16 HMMA; unchanged)
// ---------------------------------------------------------------------------
__global__ void __launch_bounds__(256, 1) gemm_xp_kernel(
    const float* __restrict__ A, const float* __restrict__ W,
    const float* __restrict__ bias, float* __restrict__ C)
{
    __shared__ __align__(1024) char sAh[128 * 128];
    __shared__ __align__(1024) char sAl[128 * 128];
    __shared__ __align__(1024) char sBh[64 * 128];
    __shared__ __align__(1024) char sBl[64 * 128];

    const int tid = threadIdx.x;
    const int wid = tid >> 5, lane = tid & 31;
    const int m0 = blockIdx.y * 128;
    const int n0 = blockIdx.x * 64;
    const int wm = (wid >> 1) * 32;
    const int wn = (wid & 1) * 32;

    const uint32_t uAh = smem_u32(sAh), uAl = smem_u32(sAl);
    const uint32_t uBh = smem_u32(sBh), uBl = smem_u32(sBl);

    const int ar = tid >> 4;
    const int ac = tid & 15;
    const float4* __restrict__ A4 = (const float4*)A;
    const float4* __restrict__ W4 = (const float4*)W;

    float c[2][4][4] = {};
    float4 pa[8], pb[4];

    #pragma unroll
    for (int p = 0; p < 8; p++)
        pa[p] = A4[(size_t)(m0 + ar + p * 16) * 256 + ac];
    #pragma unroll
    for (int p = 0; p < 4; p++)
        pb[p] = W4[(size_t)(n0 + ar + p * 16) * 256 + ac];

    for (int ch = 0; ch < 16; ch++) {
        if (ch > 0) __syncthreads();
        #pragma unroll
        for (int p = 0; p < 8; p++)
            split_store_bf(pa[p], sAh, sAl, (uint32_t)((ar + p * 16) * 128 + ac * 8));
        #pragma unroll
        for (int p = 0; p < 4; p++)
            split_store_bf(pb[p], sBh, sBl, (uint32_t)((ar + p * 16) * 128 + ac * 8));
        __syncthreads();

        if (ch < 15) {
            const int kc = (ch + 1) * 16;
            #pragma unroll
            for (int p = 0; p < 8; p++)
                pa[p] = A4[(size_t)(m0 + ar + p * 16) * 256 + kc + ac];
            #pragma unroll
            for (int p = 0; p < 4; p++)
                pb[p] = W4[(size_t)(n0 + ar + p * 16) * 256 + kc + ac];
        }

        #pragma unroll
        for (int ks = 0; ks < 4; ks++) {
            const int q = lane >> 3;
            uint32_t ah[2][4], al[2][4];
            #pragma unroll
            for (int mi = 0; mi < 2; mi++) {
                uint32_t r = (uint32_t)(wm + mi * 16 + (lane & 7) + (q & 1) * 8);
                uint32_t kb = (uint32_t)(ks * 32 + (q >> 1) * 16);
                uint32_t so = sw128(r * 128 + kb);
                ldsm4(ah[mi], uAh + so);
                ldsm4(al[mi], uAl + so);
            }
            uint32_t bhf[2][4], blf[2][4];
            #pragma unroll
            for (int g = 0; g < 2; g++) {
                uint32_t rn = (uint32_t)(wn + g * 16 + (lane & 7) + (q >> 1) * 8);
                uint32_t kb = (uint32_t)(ks * 32 + (q & 1) * 16);
                uint32_t so = sw128(rn * 128 + kb);
                ldsm4(bhf[g], uBh + so);
                ldsm4(blf[g], uBl + so);
            }
            #pragma unroll
            for (int mi = 0; mi < 2; mi++)
                #pragma unroll
                for (int ni = 0; ni < 4; ni++) {
                    uint32_t b0h = bhf[ni >> 1][(ni & 1) * 2];
                    uint32_t b1h = bhf[ni >> 1][(ni & 1) * 2 + 1];
                    uint32_t b0l = blf[ni >> 1][(ni & 1) * 2];
                    uint32_t b1l = blf[ni >> 1][(ni & 1) * 2 + 1];
                    mma_bf16(c[mi][ni], ah[mi], b0h, b1h);
                    mma_bf16(c[mi][ni], ah[mi], b0l, b1l);
                    mma_bf16(c[mi][ni], al[mi], b0h, b1h);
                }
        }
    }

    const int t4 = lane >> 2, cp = (lane & 3) * 2;
    #pragma unroll
    for (int mi = 0; mi < 2; mi++) {
        #pragma unroll
        for (int ni = 0; ni < 4; ni++) {
            const int col = n0 + wn + ni * 8 + cp;
            float2 bv = *(const float2*)&bias[col];
            const int r0 = m0 + wm + mi * 16 + t4;
            float2 v0 = make_float2(c[mi][ni][0] + bv.x, c[mi][ni][1] + bv.y);
            float2 v1 = make_float2(c[mi][ni][2] + bv.x, c[mi][ni][3] + bv.y);
            *(float2*)&C[(size_t)r0 * H_ + col] = v0;
            *(float2*)&C[(size_t)(r0 + 8) * H_ + col] = v1;
        }
    }
}

// ---------------------------------------------------------------------------
// Phase 2: persistent scan, fragment-native global A exchange.
// Grid (32, 4) = 128 CTAs, 256 threads; 8 warps (4m-rowgrps x 2n).
// No __syncthreads in the step loop: per-warp flag waits (lane0 acquire +
// syncwarp), direct ld.global.cg.v4 A-fragment loads, Wh fp16 resident in
// SMEM (read-only), one st.global.v4 per thread in the epilogue, per-warp
// release arrivals (64 warps per cohort flag).
// ---------------------------------------------------------------------------
__global__ void __launch_bounds__(256, 1) rnn_scan_kernel(
    const float* __restrict__ Wh, const float* __restrict__ bh,
    float* __restrict__ hall, float* __restrict__ hfinal)
{
    extern __shared__ __align__(1024) char smem[];

    const int tid = threadIdx.x;
    const int wid = tid >> 5, lane = tid & 31;
    const int bx = blockIdx.x;           // n-tile 0..31
    const int by = blockIdx.y;           // m-tile 0..3
    const int n0 = bx * 32;
    const int m0 = by * 64;

    const uint32_t uWh = smem_u32(smem + OFF_WH);

    // ---- one-time: round Wh tile to fp16 into resident SMEM ----
    {
        const float4* __restrict__ W4 = (const float4*)Wh;
        for (int i = tid; i < 8192; i += 256) {
            int r  = i >> 8;          // n row 0..31
            int f4 = i & 255;         // float4 col
            int c  = f4 >> 4;         // chunk 0..15
            int fc = f4 & 15;
            float4 v = W4[(size_t)(n0 + r) * 256 + f4];
            round_store_h(v, smem + OFF_WH + c * 4096,
                          (uint32_t)(r * 128 + fc * 8));
        }
    }
    __syncthreads();

    // warp mapping: 8 warps = 4m-rowgrps x 2n; warp tile 16(m) x 16(n)
    const int rowgrp = wid >> 1;         // 0..3
    const int wm = rowgrp * 16;
    const int wn = (wid & 1) * 16;
    const int t4 = lane >> 2, cp = (lane & 3) * 2;
    const int q = lane >> 3;
    float2 bv[2];
    bv[0] = *(const float2*)&bh[n0 + wn + 0 + cp];
    bv[1] = *(const float2*)&bh[n0 + wn + 8 + cp];

    // B ldsm base offsets per ksl (0..3), chunk-relative (swizzled)
    uint32_t boff[4];
    {
        uint32_t rn = (uint32_t)(wn + (lane & 7) + (q >> 1) * 8);
        #pragma unroll
        for (int ksl = 0; ksl < 4; ksl++)
            boff[ksl] = sw128(rn * 128 + (uint32_t)(ksl * 32 + (q & 1) * 16));
    }

    // epilogue frag target: kstep = bx*2 + (wn>>4)
    const int kstep_w = bx * 2 + (wn >> 4);
    // flags for this m-group
    unsigned* flags = &g_done[(by * 4) * 32];
    unsigned* myflag = &flags[(bx >> 3) * 32];

    for (int t = 0; t < TSTEPS; t++) {
        float c0[2][4] = {}, c1[2][4] = {};   // two interleaved accum sets
        float* __restrict__ xp = hall + (size_t)t * BH_;

        // prefetch xp for epilogue
        float2 xv[2][2];
        #pragma unroll
        for (int ni = 0; ni < 2; ni++)
            #pragma unroll
            for (int h = 0; h < 2; h++) {
                const int r = m0 + wm + t4 + h * 8;
                const int col = n0 + wn + ni * 8 + cp;
                xv[ni][h] = *(const float2*)&xp[(size_t)r * H_ + col];
            }

        if (t > 0) {
            const uint4* __restrict__ fbase =
                &g_frag[(t - 1) & 1][by][rowgrp][0][lane];
            const unsigned tgt = 64u * (unsigned)t;

            #pragma unroll 1
            for (int s = 0; s < 4; s++) {
                // per-warp flag wait (producer cohort s)
                if (lane == 0) {
                    unsigned cur;
                    do {
                        asm volatile("ld.acquire.gpu.u32 %0, [%1];"
                                     : "=r"(cur) : "l"(&flags[s * 32]));
                        if (cur >= tgt) break;
                        __nanosleep(16);
                    } while (true);
                }
                __syncwarp();

                // load all 16 A fragments of this stage (L2, bypass L1)
                uint4 a[16];
                #pragma unroll
                for (int i = 0; i < 16; i++)
                    a[i] = ldgcg4(fbase + (s * 16 + i) * 32);

                // compute 16 ksteps
                #pragma unroll
                for (int i = 0; i < 16; i++) {
                    const int ks = s * 16 + i;
                    const int ch = ks >> 2, ksl = ks & 3;
                    uint32_t bf[4];
                    ldsm4(bf, uWh + ch * 4096 + boff[ksl]);
                    if (i & 1) {
                        mma_f16(c1[0], (const uint32_t*)&a[i], bf[0], bf[1]);
                        mma_f16(c1[1], (const uint32_t*)&a[i], bf[2], bf[3]);
                    } else {
                        mma_f16(c0[0], (const uint32_t*)&a[i], bf[0], bf[1]);
                        mma_f16(c0[1], (const uint32_t*)&a[i], bf[2], bf[3]);
                    }
                }
            }
            #pragma unroll
            for (int ni = 0; ni < 2; ni++)
                #pragma unroll
                for (int r = 0; r < 4; r++)
                    c0[ni][r] += c1[ni][r];
        }

        // ---- epilogue: h = tanh(C + xp + bh); fp32 out + frag store ----
        {
            float v[2][2][2];   // [ni][h][pair]
            #pragma unroll
            for (int ni = 0; ni < 2; ni++) {
                const int col = n0 + wn + ni * 8 + cp;
                #pragma unroll
                for (int h = 0; h < 2; h++) {
                    const int r = m0 + wm + t4 + h * 8;
                    float v0 = tanhf(c0[ni][h * 2]     + xv[ni][h].x + bv[ni].x);
                    float v1 = tanhf(c0[ni][h * 2 + 1] + xv[ni][h].y + bv[ni].y);
                    *(float2*)&xp[(size_t)r * H_ + col] = make_float2(v0, v1);
                    if (t == TSTEPS - 1)
                        *(float2*)&hfinal[(size_t)r * H_ + col] = make_float2(v0, v1);
                    v[ni][h][0] = v0; v[ni][h][1] = v1;
                }
            }
            // fragment store: reg = h + 2*ni, one uint4 per thread
            uint4 fv;
            fv.x = pack2h(__float2half(v[0][0][0]), __float2half(v[0][0][1]));
            fv.y = pack2h(__float2half(v[0][1][0]), __float2half(v[0][1][1]));
            fv.z = pack2h(__float2half(v[1][0][0]), __float2half(v[1][0][1]));
            fv.w = pack2h(__float2half(v[1][1][0]), __float2half(v[1][1][1]));
            stg4(&g_frag[t & 1][by][rowgrp][kstep_w][lane], fv);
        }

        // per-warp arrival (release; cumulative after syncwarp)
        if (t < TSTEPS - 1) {
            __syncwarp();
            if (lane == 0)
                asm volatile("red.release.gpu.global.add.u32 [%0], %1;"
                             :: "l"(myflag), "r"(1u) : "memory");
        }
    }
}

// ---------------------------------------------------------------------------
// kernel_launch
// ---------------------------------------------------------------------------
extern "C" void kernel_launch(void* const* d_in, const int* in_sizes, int n_in,
                              void* d_out, int out_size)
{
    const float* x  = (const float*)d_in[0];
    const float* Wx = (const float*)d_in[1];
    const float* bx = (const float*)d_in[2];
    const float* Wh = (const float*)d_in[3];
    const float* bh = (const float*)d_in[4];

    float* out    = (float*)d_out;
    float* hfinal = out;                 // [B_ * H_]
    float* hall   = out + BH_;           // [TSTEPS * B_ * H_]

    static int smem_set = 0;
    if (!smem_set) {
        cudaFuncSetAttribute(rnn_scan_kernel,
                             cudaFuncAttributeMaxDynamicSharedMemorySize,
                             SMEM_TOTAL);
        smem_set = 1;
    }

    // reset flags (graph-replay determinism)
    zero_flags_kernel<<<1, 512>>>();

    // Phase 1: xp for all timesteps
    gemm_xp_kernel<<<dim3(16, 1024), 256>>>(x, Wx, bx, hall);

    // Phase 2: persistent tensor-core scan (128 CTAs, all resident)
    rnn_scan_kernel<<<dim3(32, 4), 256, SMEM_TOTAL>>>(Wh, bh, hall, hfinal);
}